// round 1
// baseline (speedup 1.0000x reference)
#include <cuda_runtime.h>
#include <math.h>
#include <float.h>

#define BB 2
#define NN 8192
#define KK 16
#define CC 64
#define BN (BB*NN)

// scratch (device globals — no runtime allocation)
__device__ float g_q[BN*CC];
__device__ float g_k[BN*CC];
__device__ float g_v[BN*CC];
__device__ int   g_idx[BN*KK];

// ---------------------------------------------------------------------------
// Kernel 1: x = feat@emb_w + emb_b ; q = x@wq ; k = x@wk ; v = x@wv
// block: 256 threads = 4 rows x 64 channels, 64 rows per block
// ---------------------------------------------------------------------------
__global__ void proj_kernel(const float* __restrict__ feat,
                            const float* __restrict__ emb_w, const float* __restrict__ emb_b,
                            const float* __restrict__ wq, const float* __restrict__ wk,
                            const float* __restrict__ wv) {
    __shared__ float sf[4][CC];
    __shared__ float sx[4][CC];
    int tid = threadIdx.x;
    int r = tid >> 6, c = tid & 63;
    int base = blockIdx.x * 64;
    for (int it = 0; it < 16; it++) {
        int row = base + it * 4 + r;
        sf[r][c] = feat[row * CC + c];
        __syncthreads();
        float acc = emb_b[c];
#pragma unroll
        for (int j = 0; j < CC; j++)
            acc = fmaf(sf[r][j], __ldg(&emb_w[j * CC + c]), acc);
        sx[r][c] = acc;
        __syncthreads();
        float aq = 0.f, ak = 0.f, av = 0.f;
#pragma unroll
        for (int j = 0; j < CC; j++) {
            float xv = sx[r][j];
            aq = fmaf(xv, __ldg(&wq[j * CC + c]), aq);
            ak = fmaf(xv, __ldg(&wk[j * CC + c]), ak);
            av = fmaf(xv, __ldg(&wv[j * CC + c]), av);
        }
        g_q[row * CC + c] = aq;
        g_k[row * CC + c] = ak;
        g_v[row * CC + c] = av;
    }
}

// ---------------------------------------------------------------------------
// Kernel 2: KNN — per-thread register top-16 insertion list.
// d2 = (sq_q + sq_c) - 2*dot, identical rounding to the reference
// (2*dot is exact, fmaf(-2,dot,s) == s - 2*dot with one rounding).
// Strict '<' keeps earliest (lowest) index on exact ties, matching top_k.
// ---------------------------------------------------------------------------
#define QPB 64
#define TS  128
__global__ void knn_kernel(const float* __restrict__ pos) {
    __shared__ float4 tile[TS];
    int b = blockIdx.y;
    int n = blockIdx.x * QPB + threadIdx.x;
    const float* pb = pos + (size_t)b * NN * 3;
    float qx = pb[n * 3 + 0], qy = pb[n * 3 + 1], qz = pb[n * 3 + 2];
    float qsq = fmaf(qz, qz, fmaf(qy, qy, qx * qx));

    float dist[KK];
    int   idx[KK];
#pragma unroll
    for (int s = 0; s < KK; s++) { dist[s] = FLT_MAX; idx[s] = 0; }

    for (int t = 0; t < NN; t += TS) {
        for (int i = threadIdx.x; i < TS; i += QPB) {
            int j = t + i;
            float cx = pb[j * 3 + 0], cy = pb[j * 3 + 1], cz = pb[j * 3 + 2];
            tile[i] = make_float4(cx, cy, cz, fmaf(cz, cz, fmaf(cy, cy, cx * cx)));
        }
        __syncthreads();
#pragma unroll 4
        for (int i = 0; i < TS; i++) {
            float4 cnd = tile[i];
            float dot = fmaf(qz, cnd.z, fmaf(qy, cnd.y, qx * cnd.x));
            float d2  = fmaf(-2.f, dot, qsq + cnd.w);
            if (d2 < dist[KK - 1]) {
                int j = t + i;
                int p = KK - 1;
#pragma unroll
                for (int s = KK - 2; s >= 0; s--)
                    if (d2 < dist[s]) p = s;
#pragma unroll
                for (int s = KK - 1; s >= 1; s--) {
                    bool here = (s == p);
                    bool sh   = (s > p);
                    dist[s] = here ? d2 : (sh ? dist[s - 1] : dist[s]);
                    idx[s]  = here ? j  : (sh ? idx[s - 1]  : idx[s]);
                }
                if (p == 0) { dist[0] = d2; idx[0] = j; }
            }
        }
        __syncthreads();
    }
#pragma unroll
    for (int s = 0; s < KK; s++)
        g_idx[((size_t)b * NN + n) * KK + s] = idx[s];
}

// ---------------------------------------------------------------------------
// Kernel 3: fused posenc + attention MLP + softmax + combine + out projection.
// 256 threads = 4 queries x 64 channels. Matvecs batched over K=16 neighbors
// to amortize weight reads (1 LDS.128 weight per 64 FMA). Weights transposed
// into SMEM with row pad 68 floats for conflict-free float4 column reads.
// ---------------------------------------------------------------------------
#define QB 4
#define ATHREADS 256
#define WPAD 68
#define SMEM_FLOATS (3*64*WPAD + 4096 + 192 + 5*64 + QB*KK*CC + QB*CC + QB*KK*4 + QB*CC + QB*KK)

__global__ void attn_kernel(const float* __restrict__ pos,
                            const float* __restrict__ feat,
                            const float* __restrict__ pe_w1, const float* __restrict__ pe_b1,
                            const float* __restrict__ pe_w2, const float* __restrict__ pe_b2,
                            const float* __restrict__ at_w1, const float* __restrict__ at_b1,
                            const float* __restrict__ at_w2, const float* __restrict__ at_b2,
                            const float* __restrict__ out_w, const float* __restrict__ out_b,
                            float* __restrict__ out) {
    extern __shared__ float sm[];
    float* wt_pe2 = sm;
    float* wt_at1 = wt_pe2 + 64 * WPAD;
    float* wt_at2 = wt_at1 + 64 * WPAD;
    float* s_outw = wt_at2 + 64 * WPAD;
    float* s_pe1w = s_outw + 4096;
    float* s_b    = s_pe1w + 192;        // pe_b1 | pe_b2 | at_b1 | at_b2 | out_b
    float* Sbuf   = s_b + 320;
    float* qbuf   = Sbuf + QB * KK * CC;
    float* relb   = qbuf + QB * CC;
    float* resb   = relb + QB * KK * 4;
    int*   idxb   = (int*)(resb + QB * CC);

    int tid = threadIdx.x;
    for (int e = tid; e < 4096; e += ATHREADS) {
        int j = e >> 6, c2 = e & 63;
        wt_pe2[c2 * WPAD + j] = pe_w2[e];
        wt_at1[c2 * WPAD + j] = at_w1[e];
        wt_at2[c2 * WPAD + j] = at_w2[e];
        s_outw[e] = out_w[e];
    }
    if (tid < 192) s_pe1w[tid] = pe_w1[tid];
    if (tid < 64) {
        s_b[tid]       = pe_b1[tid];
        s_b[64 + tid]  = pe_b2[tid];
        s_b[128 + tid] = at_b1[tid];
        s_b[192 + tid] = at_b2[tid];
        s_b[256 + tid] = out_b[tid];
    }

    int ql = tid >> 6;
    int c  = tid & 63;
    int g  = blockIdx.x * QB + ql;
    int bbase = g & ~(NN - 1);

    qbuf[ql * CC + c] = g_q[(size_t)g * CC + c];
    if (c < KK) {
        int k = c;
        int ii = g_idx[(size_t)g * KK + k];
        idxb[ql * KK + k] = ii;
        size_t np = (size_t)(bbase + ii) * 3;
        size_t qp = (size_t)g * 3;
        relb[(ql * KK + k) * 4 + 0] = pos[np + 0] - pos[qp + 0];
        relb[(ql * KK + k) * 4 + 1] = pos[np + 1] - pos[qp + 1];
        relb[(ql * KK + k) * 4 + 2] = pos[np + 2] - pos[qp + 2];
    }
    __syncthreads();

    float* S = Sbuf + ql * KK * CC;

    // Stage A: pe1 = relu(rel @ pe_w1 + pe_b1) -> S
    {
        float w0 = s_pe1w[0 * CC + c], w1 = s_pe1w[1 * CC + c], w2 = s_pe1w[2 * CC + c];
        float b1v = s_b[c];
#pragma unroll
        for (int k = 0; k < KK; k++) {
            float v = b1v;
            v = fmaf(relb[(ql * KK + k) * 4 + 0], w0, v);
            v = fmaf(relb[(ql * KK + k) * 4 + 1], w1, v);
            v = fmaf(relb[(ql * KK + k) * 4 + 2], w2, v);
            S[k * CC + c] = fmaxf(v, 0.f);
        }
    }
    __syncthreads();

    // Stage B: posenc = pe1 @ pe_w2 + pe_b2 (registers)
    float pen[KK];
#pragma unroll
    for (int k = 0; k < KK; k++) pen[k] = 0.f;
    {
        const float* wrow = wt_pe2 + c * WPAD;
        for (int j4 = 0; j4 < 16; j4++) {
            float4 w4 = *(const float4*)(wrow + j4 * 4);
#pragma unroll
            for (int k = 0; k < KK; k++) {
                float4 s4 = *(const float4*)(S + k * CC + j4 * 4);
                pen[k] = fmaf(s4.x, w4.x, fmaf(s4.y, w4.y, fmaf(s4.z, w4.z, fmaf(s4.w, w4.w, pen[k]))));
            }
        }
        float b2v = s_b[64 + c];
#pragma unroll
        for (int k = 0; k < KK; k++) pen[k] += b2v;
    }
    __syncthreads();

    // Stage C: h = q - k_feat + posenc -> S
    {
        float qc = qbuf[ql * CC + c];
#pragma unroll
        for (int k = 0; k < KK; k++) {
            int ii = idxb[ql * KK + k];
            float kf = __ldg(&g_k[(size_t)(bbase + ii) * CC + c]);
            S[k * CC + c] = qc - kf + pen[k];
        }
    }
    __syncthreads();

    // Stage D: a1 = relu(h @ at_w1 + at_b1)
    float acc[KK];
#pragma unroll
    for (int k = 0; k < KK; k++) acc[k] = 0.f;
    {
        const float* wrow = wt_at1 + c * WPAD;
        for (int j4 = 0; j4 < 16; j4++) {
            float4 w4 = *(const float4*)(wrow + j4 * 4);
#pragma unroll
            for (int k = 0; k < KK; k++) {
                float4 s4 = *(const float4*)(S + k * CC + j4 * 4);
                acc[k] = fmaf(s4.x, w4.x, fmaf(s4.y, w4.y, fmaf(s4.z, w4.z, fmaf(s4.w, w4.w, acc[k]))));
            }
        }
        float bv = s_b[128 + c];
#pragma unroll
        for (int k = 0; k < KK; k++) acc[k] = fmaxf(acc[k] + bv, 0.f);
    }
    __syncthreads();
#pragma unroll
    for (int k = 0; k < KK; k++) S[k * CC + c] = acc[k];
    __syncthreads();

    // Stage E: logits = a1 @ at_w2 + at_b2 (scaled by 1/sqrt(64))
#pragma unroll
    for (int k = 0; k < KK; k++) acc[k] = 0.f;
    {
        const float* wrow = wt_at2 + c * WPAD;
        for (int j4 = 0; j4 < 16; j4++) {
            float4 w4 = *(const float4*)(wrow + j4 * 4);
#pragma unroll
            for (int k = 0; k < KK; k++) {
                float4 s4 = *(const float4*)(S + k * CC + j4 * 4);
                acc[k] = fmaf(s4.x, w4.x, fmaf(s4.y, w4.y, fmaf(s4.z, w4.z, fmaf(s4.w, w4.w, acc[k]))));
            }
        }
        float bv = s_b[192 + c];
#pragma unroll
        for (int k = 0; k < KK; k++) acc[k] = (acc[k] + bv) * 0.125f;
    }

    // softmax over K (per channel, register-local) + weighted combine
    float m = acc[0];
#pragma unroll
    for (int k = 1; k < KK; k++) m = fmaxf(m, acc[k]);
    float ssum = 0.f;
#pragma unroll
    for (int k = 0; k < KK; k++) { acc[k] = __expf(acc[k] - m); ssum += acc[k]; }
    float inv = 1.f / ssum;
    float res = 0.f;
#pragma unroll
    for (int k = 0; k < KK; k++) {
        int ii = idxb[ql * KK + k];
        float vv = __ldg(&g_v[(size_t)(bbase + ii) * CC + c]);
        res = fmaf(acc[k] * inv, vv + pen[k], res);
    }
    resb[ql * CC + c] = res;
    __syncthreads();

    // final: out = res @ out_w + out_b + features (residual)
    {
        float o = s_b[256 + c];
#pragma unroll
        for (int j = 0; j < CC; j++)
            o = fmaf(resb[ql * CC + j], s_outw[j * CC + c], o);
        out[(size_t)g * CC + c] = o + feat[(size_t)g * CC + c];
    }
}

// ---------------------------------------------------------------------------
extern "C" void kernel_launch(void* const* d_in, const int* in_sizes, int n_in,
                              void* d_out, int out_size) {
    const float* pos   = (const float*)d_in[0];
    const float* feat  = (const float*)d_in[1];
    const float* emb_w = (const float*)d_in[2];
    const float* emb_b = (const float*)d_in[3];
    const float* wq    = (const float*)d_in[4];
    const float* wk    = (const float*)d_in[5];
    const float* wv    = (const float*)d_in[6];
    const float* pe_w1 = (const float*)d_in[7];
    const float* pe_b1 = (const float*)d_in[8];
    const float* pe_w2 = (const float*)d_in[9];
    const float* pe_b2 = (const float*)d_in[10];
    const float* at_w1 = (const float*)d_in[11];
    const float* at_b1 = (const float*)d_in[12];
    const float* at_w2 = (const float*)d_in[13];
    const float* at_b2 = (const float*)d_in[14];
    const float* out_w = (const float*)d_in[15];
    const float* out_b = (const float*)d_in[16];
    float* out = (float*)d_out;

    int smem_bytes = SMEM_FLOATS * 4;
    cudaFuncSetAttribute(attn_kernel, cudaFuncAttributeMaxDynamicSharedMemorySize, smem_bytes);

    proj_kernel<<<BN / 64, 256>>>(feat, emb_w, emb_b, wq, wk, wv);
    knn_kernel<<<dim3(NN / QPB, BB), QPB>>>(pos);
    attn_kernel<<<BN / QB, ATHREADS, smem_bytes>>>(pos, feat, pe_w1, pe_b1, pe_w2, pe_b2,
                                                   at_w1, at_b1, at_w2, at_b2, out_w, out_b, out);
}

// round 2
// speedup vs baseline: 1.1110x; 1.1110x over previous
#include <cuda_runtime.h>
#include <math.h>
#include <float.h>

#define BB 2
#define NN 8192
#define KK 16
#define CC 64
#define BN (BB*NN)
#define CH 4
#define CHS (NN/CH)

typedef unsigned long long ull;

__device__ __forceinline__ ull pk(float a, float b) {
    ull d; asm("mov.b64 %0,{%1,%2};" : "=l"(d) : "f"(a), "f"(b)); return d;
}
__device__ __forceinline__ void upk(ull s, float& a, float& b) {
    asm("mov.b64 {%0,%1},%2;" : "=f"(a), "=f"(b) : "l"(s));
}
__device__ __forceinline__ ull f2fma(ull a, ull b, ull c) {
    ull d; asm("fma.rn.f32x2 %0,%1,%2,%3;" : "=l"(d) : "l"(a), "l"(b), "l"(c)); return d;
}
__device__ __forceinline__ ull f2add(ull a, ull b) {
    ull d; asm("add.rn.f32x2 %0,%1,%2;" : "=l"(d) : "l"(a), "l"(b)); return d;
}

// scratch (device globals — no runtime allocation)
__device__ float g_q[BN*CC];
__device__ float g_k[BN*CC];
__device__ float g_v[BN*CC];
__device__ int   g_idx[BN*KK];
__device__ float g_pd[BN*CH*KK];
__device__ int   g_pi[BN*CH*KK];

// ---------------------------------------------------------------------------
// Kernel 1: x = feat@emb_w + emb_b ; q/k/v = x@wq/wk/wv.
// Weights transposed into SMEM with pad-68 rows: lane c reads float4 at
// wt[c*68 + 4*j4] -> quarter-warp covers all 32 banks, conflict-free.
// ---------------------------------------------------------------------------
#define PWPAD 68
__global__ void __launch_bounds__(256) proj_kernel(
        const float* __restrict__ feat,
        const float* __restrict__ emb_w, const float* __restrict__ emb_b,
        const float* __restrict__ wq, const float* __restrict__ wk,
        const float* __restrict__ wv) {
    extern __shared__ float ps[];
    float* we  = ps;
    float* wqt = we  + 64 * PWPAD;
    float* wkt = wqt + 64 * PWPAD;
    float* wvt = wkt + 64 * PWPAD;
    __shared__ __align__(16) float sf[4][CC];
    __shared__ __align__(16) float sx[4][CC];
    __shared__ float sb[CC];

    int tid = threadIdx.x;
    for (int e = tid; e < 4096; e += 256) {
        int j = e >> 6, c2 = e & 63;
        we[c2 * PWPAD + j]  = emb_w[e];
        wqt[c2 * PWPAD + j] = wq[e];
        wkt[c2 * PWPAD + j] = wk[e];
        wvt[c2 * PWPAD + j] = wv[e];
    }
    if (tid < 64) sb[tid] = emb_b[tid];
    __syncthreads();

    int r = tid >> 6, c = tid & 63;
    int base = blockIdx.x * 64;
    const float* wre = we  + c * PWPAD;
    const float* wrq = wqt + c * PWPAD;
    const float* wrk = wkt + c * PWPAD;
    const float* wrv = wvt + c * PWPAD;

    for (int it = 0; it < 16; it++) {
        int row = base + it * 4 + r;
        sf[r][c] = feat[row * CC + c];
        __syncthreads();
        float acc = sb[c];
#pragma unroll
        for (int j4 = 0; j4 < 16; j4++) {
            float4 x4 = *(const float4*)(&sf[r][j4 * 4]);
            float4 w4 = *(const float4*)(wre + j4 * 4);
            acc = fmaf(x4.x, w4.x, acc);
            acc = fmaf(x4.y, w4.y, acc);
            acc = fmaf(x4.z, w4.z, acc);
            acc = fmaf(x4.w, w4.w, acc);
        }
        sx[r][c] = acc;
        __syncthreads();
        float aq = 0.f, ak = 0.f, av = 0.f;
#pragma unroll
        for (int j4 = 0; j4 < 16; j4++) {
            float4 x4 = *(const float4*)(&sx[r][j4 * 4]);
            float4 q4 = *(const float4*)(wrq + j4 * 4);
            float4 k4 = *(const float4*)(wrk + j4 * 4);
            float4 v4 = *(const float4*)(wrv + j4 * 4);
            aq = fmaf(x4.x, q4.x, aq); aq = fmaf(x4.y, q4.y, aq);
            aq = fmaf(x4.z, q4.z, aq); aq = fmaf(x4.w, q4.w, aq);
            ak = fmaf(x4.x, k4.x, ak); ak = fmaf(x4.y, k4.y, ak);
            ak = fmaf(x4.z, k4.z, ak); ak = fmaf(x4.w, k4.w, ak);
            av = fmaf(x4.x, v4.x, av); av = fmaf(x4.y, v4.y, av);
            av = fmaf(x4.z, v4.z, av); av = fmaf(x4.w, v4.w, av);
        }
        g_q[row * CC + c] = aq;
        g_k[row * CC + c] = ak;
        g_v[row * CC + c] = av;
    }
}

// ---------------------------------------------------------------------------
// Kernel 2a: partial KNN over one of CH candidate chunks (index-ordered).
// Same distance formula as the reference (boundary sets matched in R1).
// ---------------------------------------------------------------------------
#define QPB 64
#define TS  128
__global__ void knn_part(const float* __restrict__ pos) {
    __shared__ float4 tile[TS];
    int b  = blockIdx.z;
    int ch = blockIdx.y;
    int n  = blockIdx.x * QPB + threadIdx.x;
    const float* pb = pos + (size_t)b * NN * 3;
    float qx = pb[n * 3 + 0], qy = pb[n * 3 + 1], qz = pb[n * 3 + 2];
    float qsq = fmaf(qz, qz, fmaf(qy, qy, qx * qx));

    float dist[KK];
    int   idx[KK];
#pragma unroll
    for (int s = 0; s < KK; s++) { dist[s] = FLT_MAX; idx[s] = 0; }

    int c0 = ch * CHS;
    for (int t = c0; t < c0 + CHS; t += TS) {
        for (int i = threadIdx.x; i < TS; i += QPB) {
            int j = t + i;
            float cx = pb[j * 3 + 0], cy = pb[j * 3 + 1], cz = pb[j * 3 + 2];
            tile[i] = make_float4(cx, cy, cz, fmaf(cz, cz, fmaf(cy, cy, cx * cx)));
        }
        __syncthreads();
#pragma unroll 8
        for (int i = 0; i < TS; i++) {
            float4 cnd = tile[i];
            float dot = fmaf(qz, cnd.z, fmaf(qy, cnd.y, qx * cnd.x));
            float d2  = fmaf(-2.f, dot, qsq + cnd.w);
            if (d2 < dist[KK - 1]) {
                int j = t + i;
                int p = KK - 1;
#pragma unroll
                for (int s = KK - 2; s >= 0; s--)
                    if (d2 < dist[s]) p = s;
#pragma unroll
                for (int s = KK - 1; s >= 1; s--) {
                    bool here = (s == p);
                    bool sh   = (s > p);
                    dist[s] = here ? d2 : (sh ? dist[s - 1] : dist[s]);
                    idx[s]  = here ? j  : (sh ? idx[s - 1]  : idx[s]);
                }
                if (p == 0) { dist[0] = d2; idx[0] = j; }
            }
        }
        __syncthreads();
    }
    size_t o = (((size_t)b * NN + n) * CH + ch) * KK;
#pragma unroll
    for (int s = 0; s < KK; s++) { g_pd[o + s] = dist[s]; g_pi[o + s] = idx[s]; }
}

// Kernel 2b: stable merge of CH partial top-16 lists -> global top-16.
__global__ void knn_merge() {
    int q = blockIdx.x * 256 + threadIdx.x;
    float dist[KK];
    int   idx[KK];
#pragma unroll
    for (int s = 0; s < KK; s++) { dist[s] = FLT_MAX; idx[s] = 0; }
    size_t o = (size_t)q * CH * KK;
    for (int e = 0; e < CH * KK; e++) {
        float d2 = g_pd[o + e];
        int   j  = g_pi[o + e];
        if (d2 < dist[KK - 1]) {
            int p = KK - 1;
#pragma unroll
            for (int s = KK - 2; s >= 0; s--)
                if (d2 < dist[s]) p = s;
#pragma unroll
            for (int s = KK - 1; s >= 1; s--) {
                bool here = (s == p);
                bool sh   = (s > p);
                dist[s] = here ? d2 : (sh ? dist[s - 1] : dist[s]);
                idx[s]  = here ? j  : (sh ? idx[s - 1]  : idx[s]);
            }
            if (p == 0) { dist[0] = d2; idx[0] = j; }
        }
    }
#pragma unroll
    for (int s = 0; s < KK; s++) g_idx[(size_t)q * KK + s] = idx[s];
}

// ---------------------------------------------------------------------------
// Kernel 3: fused posenc + attn MLPs + softmax + combine + out projection.
// 1 warp per query; lane l owns channels l and l+32; K packed as f32x2 pairs.
// Stage buffer Sp2[j][kp] = (S[2kp][j], S[2kp+1][j]) as float2, stride 9.
// Hot loop: 8 bcast LDS.64 + 2 LDS.32 + 2 packs + 16 FFMA2 per j.
// ---------------------------------------------------------------------------
#define AQ 8
#define SQSTRIDE 576   // 64*9 ull per query

__device__ __forceinline__ void mv16x64(const ull* __restrict__ Sq,
                                        const float* __restrict__ w, int l,
                                        ull aL[8], ull aH[8]) {
#pragma unroll
    for (int kp = 0; kp < 8; kp++) { aL[kp] = 0ull; aH[kp] = 0ull; }
#pragma unroll 4
    for (int j = 0; j < 64; j++) {
        float wl = w[j * 64 + l];
        float wh = w[j * 64 + l + 32];
        ull wl2 = pk(wl, wl);
        ull wh2 = pk(wh, wh);
        const ull* s = Sq + j * 9;
#pragma unroll
        for (int kp = 0; kp < 8; kp++) {
            ull s2 = s[kp];
            aL[kp] = f2fma(s2, wl2, aL[kp]);
            aH[kp] = f2fma(s2, wh2, aH[kp]);
        }
    }
}

__global__ void __launch_bounds__(256) attn_kernel(
        const float* __restrict__ pos, const float* __restrict__ feat,
        const float* __restrict__ pe_w1, const float* __restrict__ pe_b1,
        const float* __restrict__ pe_w2, const float* __restrict__ pe_b2,
        const float* __restrict__ at_w1, const float* __restrict__ at_b1,
        const float* __restrict__ at_w2, const float* __restrict__ at_b2,
        const float* __restrict__ out_w, const float* __restrict__ out_b,
        float* __restrict__ out) {
    extern __shared__ float sm[];
    float* w_pe2 = sm;
    float* w_at1 = w_pe2 + 4096;
    float* w_at2 = w_at1 + 4096;
    float* w_out = w_at2 + 4096;
    float* s_pe1 = w_out + 4096;       // 192
    float* s_b   = s_pe1 + 192;        // 320: pe_b1|pe_b2|at_b1|at_b2|out_b
    ull*   Sp2   = (ull*)(s_b + 320);  // AQ * 576 ull
    float* relb  = (float*)(Sp2 + AQ * SQSTRIDE); // AQ*16*4
    float* resb  = relb + AQ * KK * 4;            // AQ*64
    int*   idxb  = (int*)(resb + AQ * CC);        // AQ*16

    int tid = threadIdx.x;
    for (int e = tid; e < 4096; e += 256) {
        w_pe2[e] = pe_w2[e];
        w_at1[e] = at_w1[e];
        w_at2[e] = at_w2[e];
        w_out[e] = out_w[e];
    }
    if (tid < 192) s_pe1[tid] = pe_w1[tid];
    if (tid < 64) {
        s_b[tid]       = pe_b1[tid];
        s_b[64 + tid]  = pe_b2[tid];
        s_b[128 + tid] = at_b1[tid];
        s_b[192 + tid] = at_b2[tid];
        s_b[256 + tid] = out_b[tid];
    }

    int wid = tid >> 5;            // query slot in block
    int l   = tid & 31;
    int g   = blockIdx.x * AQ + wid;
    int bbase = g & ~(NN - 1);

    float q_lo = g_q[(size_t)g * CC + l];
    float q_hi = g_q[(size_t)g * CC + l + 32];

    if (l < KK) {
        int k = l;
        int ii = g_idx[(size_t)g * KK + k];
        idxb[wid * KK + k] = ii;
        size_t np = (size_t)(bbase + ii) * 3;
        size_t qp = (size_t)g * 3;
        relb[(wid * KK + k) * 4 + 0] = pos[np + 0] - pos[qp + 0];
        relb[(wid * KK + k) * 4 + 1] = pos[np + 1] - pos[qp + 1];
        relb[(wid * KK + k) * 4 + 2] = pos[np + 2] - pos[qp + 2];
    }
    __syncthreads();

    ull* Sq = Sp2 + wid * SQSTRIDE;

    // Stage A: pe1 = relu(rel @ pe_w1 + pe_b1) -> Sq (packed k-pairs)
    {
        float w0l = s_pe1[l],        w1l = s_pe1[64 + l],        w2l = s_pe1[128 + l];
        float w0h = s_pe1[l + 32],   w1h = s_pe1[96 + l],        w2h = s_pe1[160 + l];
        float b1l = s_b[l], b1h = s_b[l + 32];
#pragma unroll
        for (int kp = 0; kp < 8; kp++) {
            const float* ra = relb + (wid * KK + 2 * kp) * 4;
            const float* rb = ra + 4;
            float pa = fmaxf(fmaf(ra[2], w2l, fmaf(ra[1], w1l, fmaf(ra[0], w0l, b1l))), 0.f);
            float pb = fmaxf(fmaf(rb[2], w2l, fmaf(rb[1], w1l, fmaf(rb[0], w0l, b1l))), 0.f);
            Sq[l * 9 + kp] = pk(pa, pb);
            float qa = fmaxf(fmaf(ra[2], w2h, fmaf(ra[1], w1h, fmaf(ra[0], w0h, b1h))), 0.f);
            float qb = fmaxf(fmaf(rb[2], w2h, fmaf(rb[1], w1h, fmaf(rb[0], w0h, b1h))), 0.f);
            Sq[(l + 32) * 9 + kp] = pk(qa, qb);
        }
    }
    __syncwarp();

    // Stage B: posenc = pe1 @ pe_w2 + pe_b2 (packed accumulators)
    ull penL[8], penH[8];
    mv16x64(Sq, w_pe2, l, penL, penH);
    {
        ull b2l = pk(s_b[64 + l], s_b[64 + l]);
        ull b2h = pk(s_b[64 + l + 32], s_b[64 + l + 32]);
#pragma unroll
        for (int kp = 0; kp < 8; kp++) {
            penL[kp] = f2add(penL[kp], b2l);
            penH[kp] = f2add(penH[kp], b2h);
        }
    }
    __syncwarp();

    // Stage C: h = q - k_feat + posenc -> Sq
#pragma unroll
    for (int kp = 0; kp < 8; kp++) {
        int i0 = idxb[wid * KK + 2 * kp];
        int i1 = idxb[wid * KK + 2 * kp + 1];
        float k0l = g_k[(size_t)(bbase + i0) * CC + l];
        float k1l = g_k[(size_t)(bbase + i1) * CC + l];
        float k0h = g_k[(size_t)(bbase + i0) * CC + l + 32];
        float k1h = g_k[(size_t)(bbase + i1) * CC + l + 32];
        float p0, p1;
        upk(penL[kp], p0, p1);
        Sq[l * 9 + kp] = pk(q_lo - k0l + p0, q_lo - k1l + p1);
        upk(penH[kp], p0, p1);
        Sq[(l + 32) * 9 + kp] = pk(q_hi - k0h + p0, q_hi - k1h + p1);
    }
    __syncwarp();

    // Stage D: a1 = relu(h @ at_w1 + at_b1) -> Sq
    ull aL[8], aH[8];
    mv16x64(Sq, w_at1, l, aL, aH);
    __syncwarp();
    {
        float bl = s_b[128 + l], bh = s_b[128 + l + 32];
#pragma unroll
        for (int kp = 0; kp < 8; kp++) {
            float x, y;
            upk(aL[kp], x, y);
            Sq[l * 9 + kp] = pk(fmaxf(x + bl, 0.f), fmaxf(y + bl, 0.f));
            upk(aH[kp], x, y);
            Sq[(l + 32) * 9 + kp] = pk(fmaxf(x + bh, 0.f), fmaxf(y + bh, 0.f));
        }
    }
    __syncwarp();

    // Stage E: logits = (a1 @ at_w2 + at_b2) / 8
    mv16x64(Sq, w_at2, l, aL, aH);
    float el[KK], eh[KK];
    {
        float bl = s_b[192 + l], bh = s_b[192 + l + 32];
#pragma unroll
        for (int kp = 0; kp < 8; kp++) {
            float x, y;
            upk(aL[kp], x, y);
            el[2 * kp] = (x + bl) * 0.125f; el[2 * kp + 1] = (y + bl) * 0.125f;
            upk(aH[kp], x, y);
            eh[2 * kp] = (x + bh) * 0.125f; eh[2 * kp + 1] = (y + bh) * 0.125f;
        }
    }

    // softmax over K per channel + combine with (v + posenc)
    float ml = el[0], mh = eh[0];
#pragma unroll
    for (int k = 1; k < KK; k++) { ml = fmaxf(ml, el[k]); mh = fmaxf(mh, eh[k]); }
    float sl = 0.f, sh = 0.f;
#pragma unroll
    for (int k = 0; k < KK; k++) {
        el[k] = __expf(el[k] - ml); sl += el[k];
        eh[k] = __expf(eh[k] - mh); sh += eh[k];
    }
    float il = 1.f / sl, ih = 1.f / sh;
    float res_lo = 0.f, res_hi = 0.f;
#pragma unroll
    for (int kp = 0; kp < 8; kp++) {
        int i0 = idxb[wid * KK + 2 * kp];
        int i1 = idxb[wid * KK + 2 * kp + 1];
        float v0l = g_v[(size_t)(bbase + i0) * CC + l];
        float v1l = g_v[(size_t)(bbase + i1) * CC + l];
        float v0h = g_v[(size_t)(bbase + i0) * CC + l + 32];
        float v1h = g_v[(size_t)(bbase + i1) * CC + l + 32];
        float p0, p1;
        upk(penL[kp], p0, p1);
        res_lo = fmaf(el[2 * kp] * il,     v0l + p0, res_lo);
        res_lo = fmaf(el[2 * kp + 1] * il, v1l + p1, res_lo);
        upk(penH[kp], p0, p1);
        res_hi = fmaf(eh[2 * kp] * ih,     v0h + p0, res_hi);
        res_hi = fmaf(eh[2 * kp + 1] * ih, v1h + p1, res_hi);
    }
    resb[wid * CC + l] = res_lo;
    resb[wid * CC + l + 32] = res_hi;
    __syncwarp();

    // final: out = res @ out_w + out_b + features
    {
        float ol = s_b[256 + l], oh = s_b[256 + l + 32];
#pragma unroll 4
        for (int j = 0; j < 64; j++) {
            float rj = resb[wid * CC + j];
            ol = fmaf(rj, w_out[j * 64 + l], ol);
            oh = fmaf(rj, w_out[j * 64 + l + 32], oh);
        }
        out[(size_t)g * CC + l]      = ol + feat[(size_t)g * CC + l];
        out[(size_t)g * CC + l + 32] = oh + feat[(size_t)g * CC + l + 32];
    }
}

// ---------------------------------------------------------------------------
extern "C" void kernel_launch(void* const* d_in, const int* in_sizes, int n_in,
                              void* d_out, int out_size) {
    const float* pos   = (const float*)d_in[0];
    const float* feat  = (const float*)d_in[1];
    const float* emb_w = (const float*)d_in[2];
    const float* emb_b = (const float*)d_in[3];
    const float* wq    = (const float*)d_in[4];
    const float* wk    = (const float*)d_in[5];
    const float* wv    = (const float*)d_in[6];
    const float* pe_w1 = (const float*)d_in[7];
    const float* pe_b1 = (const float*)d_in[8];
    const float* pe_w2 = (const float*)d_in[9];
    const float* pe_b2 = (const float*)d_in[10];
    const float* at_w1 = (const float*)d_in[11];
    const float* at_b1 = (const float*)d_in[12];
    const float* at_w2 = (const float*)d_in[13];
    const float* at_b2 = (const float*)d_in[14];
    const float* out_w = (const float*)d_in[15];
    const float* out_b = (const float*)d_in[16];
    float* out = (float*)d_out;

    int proj_smem = 4 * 64 * PWPAD * 4;
    int attn_smem = (4096 * 4 + 192 + 320) * 4 + AQ * SQSTRIDE * 8
                  + (AQ * KK * 4 + AQ * CC) * 4 + AQ * KK * 4;
    cudaFuncSetAttribute(proj_kernel, cudaFuncAttributeMaxDynamicSharedMemorySize, proj_smem);
    cudaFuncSetAttribute(attn_kernel, cudaFuncAttributeMaxDynamicSharedMemorySize, attn_smem);

    proj_kernel<<<BN / 64, 256, proj_smem>>>(feat, emb_w, emb_b, wq, wk, wv);
    knn_part<<<dim3(NN / QPB, CH, BB), QPB>>>(pos);
    knn_merge<<<BN / 256, 256>>>();
    attn_kernel<<<BN / AQ, 256, attn_smem>>>(pos, feat, pe_w1, pe_b1, pe_w2, pe_b2,
                                             at_w1, at_b1, at_w2, at_b2, out_w, out_b, out);
}

// round 3
// speedup vs baseline: 2.1080x; 1.8973x over previous
#include <cuda_runtime.h>
#include <math.h>
#include <float.h>

#define BB 2
#define NN 8192
#define KK 16
#define CC 64
#define BN (BB*NN)

typedef unsigned long long ull;

__device__ __forceinline__ ull pk(float a, float b) {
    ull d; asm("mov.b64 %0,{%1,%2};" : "=l"(d) : "f"(a), "f"(b)); return d;
}
__device__ __forceinline__ void upk(ull s, float& a, float& b) {
    asm("mov.b64 {%0,%1},%2;" : "=f"(a), "=f"(b) : "l"(s));
}
__device__ __forceinline__ ull f2fma(ull a, ull b, ull c) {
    ull d; asm("fma.rn.f32x2 %0,%1,%2,%3;" : "=l"(d) : "l"(a), "l"(b), "l"(c)); return d;
}
__device__ __forceinline__ ull f2add(ull a, ull b) {
    ull d; asm("add.rn.f32x2 %0,%1,%2;" : "=l"(d) : "l"(a), "l"(b)); return d;
}

// scratch (device globals — no runtime allocation)
__device__ float g_q[BN*CC];
__device__ float g_k[BN*CC];
__device__ float g_v[BN*CC];
__device__ int   g_idx[BN*KK];

// ---------------------------------------------------------------------------
// Kernel 1: x = feat@emb_w + emb_b ; q/k/v = x@wq/wk/wv.
// ---------------------------------------------------------------------------
#define PWPAD 68
__global__ void __launch_bounds__(256) proj_kernel(
        const float* __restrict__ feat,
        const float* __restrict__ emb_w, const float* __restrict__ emb_b,
        const float* __restrict__ wq, const float* __restrict__ wk,
        const float* __restrict__ wv) {
    extern __shared__ float ps[];
    float* we  = ps;
    float* wqt = we  + 64 * PWPAD;
    float* wkt = wqt + 64 * PWPAD;
    float* wvt = wkt + 64 * PWPAD;
    __shared__ __align__(16) float sf[4][CC];
    __shared__ __align__(16) float sx[4][CC];
    __shared__ float sb[CC];

    int tid = threadIdx.x;
    for (int e = tid; e < 4096; e += 256) {
        int j = e >> 6, c2 = e & 63;
        we[c2 * PWPAD + j]  = emb_w[e];
        wqt[c2 * PWPAD + j] = wq[e];
        wkt[c2 * PWPAD + j] = wk[e];
        wvt[c2 * PWPAD + j] = wv[e];
    }
    if (tid < 64) sb[tid] = emb_b[tid];
    __syncthreads();

    int r = tid >> 6, c = tid & 63;
    int base = blockIdx.x * 64;
    const float* wre = we  + c * PWPAD;
    const float* wrq = wqt + c * PWPAD;
    const float* wrk = wkt + c * PWPAD;
    const float* wrv = wvt + c * PWPAD;

    for (int it = 0; it < 16; it++) {
        int row = base + it * 4 + r;
        sf[r][c] = feat[row * CC + c];
        __syncthreads();
        float acc = sb[c];
#pragma unroll
        for (int j4 = 0; j4 < 16; j4++) {
            float4 x4 = *(const float4*)(&sf[r][j4 * 4]);
            float4 w4 = *(const float4*)(wre + j4 * 4);
            acc = fmaf(x4.x, w4.x, acc);
            acc = fmaf(x4.y, w4.y, acc);
            acc = fmaf(x4.z, w4.z, acc);
            acc = fmaf(x4.w, w4.w, acc);
        }
        sx[r][c] = acc;
        __syncthreads();
        float aq = 0.f, ak = 0.f, av = 0.f;
#pragma unroll
        for (int j4 = 0; j4 < 16; j4++) {
            float4 x4 = *(const float4*)(&sx[r][j4 * 4]);
            float4 q4 = *(const float4*)(wrq + j4 * 4);
            float4 k4 = *(const float4*)(wrk + j4 * 4);
            float4 v4 = *(const float4*)(wrv + j4 * 4);
            aq = fmaf(x4.x, q4.x, aq); aq = fmaf(x4.y, q4.y, aq);
            aq = fmaf(x4.z, q4.z, aq); aq = fmaf(x4.w, q4.w, aq);
            ak = fmaf(x4.x, k4.x, ak); ak = fmaf(x4.y, k4.y, ak);
            ak = fmaf(x4.z, k4.z, ak); ak = fmaf(x4.w, k4.w, ak);
            av = fmaf(x4.x, v4.x, av); av = fmaf(x4.y, v4.y, av);
            av = fmaf(x4.z, v4.z, av); av = fmaf(x4.w, v4.w, av);
        }
        g_q[row * CC + c] = aq;
        g_k[row * CC + c] = ak;
        g_v[row * CC + c] = av;
    }
}

// ---------------------------------------------------------------------------
// Kernel 2: KNN, warp-per-query with shared threshold + rank-select merge.
// Lanes scan 32 candidates/step; a candidate is buffered iff d2 < theta
// (theta = current exact 16th-best). Merge ranks (d2, idx) lexicographically,
// exactly replicating top_k's lowest-index tie-break. d2 formula is the
// R1-validated bit-exact one: fmaf(-2, dot, qsq + csq).
// ---------------------------------------------------------------------------
#define KTS 1024
#define KWARPS 8
#define FSLOTS 80   // 16 top + up to 64 buffered

__device__ __forceinline__ void knn_flush(float* wd, int* wi, int& bc,
                                          float& theta, int lane) {
    int n = 16 + bc;
    int i0 = lane, i1 = lane + 32, i2 = lane + 64;
    bool v0 = i0 < n, v1 = i1 < n, v2 = i2 < n;
    float ed0 = v0 ? wd[i0] : 0.f;  int ei0 = v0 ? wi[i0] : 0;
    float ed1 = v1 ? wd[i1] : 0.f;  int ei1 = v1 ? wi[i1] : 0;
    float ed2 = v2 ? wd[i2] : 0.f;  int ei2 = v2 ? wi[i2] : 0;
    int r0 = 0, r1 = 0, r2 = 0;
    for (int j = 0; j < n; j++) {
        float dj = wd[j]; int ij = wi[j];
        r0 += (dj < ed0) || (dj == ed0 && ij < ei0);
        r1 += (dj < ed1) || (dj == ed1 && ij < ei1);
        r2 += (dj < ed2) || (dj == ed2 && ij < ei2);
    }
    __syncwarp();
    if (v0 && r0 < 16) { wd[r0] = ed0; wi[r0] = ei0; }
    if (v1 && r1 < 16) { wd[r1] = ed1; wi[r1] = ei1; }
    if (v2 && r2 < 16) { wd[r2] = ed2; wi[r2] = ei2; }
    __syncwarp();
    theta = wd[15];
    bc = 0;
}

__global__ void __launch_bounds__(256) knn_kernel(const float* __restrict__ pos) {
    __shared__ float4 tile[KTS];
    __shared__ float fd[KWARPS][FSLOTS];
    __shared__ int   fi[KWARPS][FSLOTS];

    int tid = threadIdx.x, lane = tid & 31, w = tid >> 5;
    int b = blockIdx.y;
    int q = blockIdx.x * KWARPS + w;
    const float* pb = pos + (size_t)b * NN * 3;
    float qx = pb[q * 3 + 0], qy = pb[q * 3 + 1], qz = pb[q * 3 + 2];
    float qsq = fmaf(qz, qz, fmaf(qy, qy, qx * qx));

    float* wd = fd[w];
    int*   wi = fi[w];
    if (lane < 16) { wd[lane] = FLT_MAX; wi[lane] = -1 - lane; }
    __syncwarp();

    float theta = FLT_MAX;
    int bc = 0;

    for (int t0 = 0; t0 < NN; t0 += KTS) {
        __syncthreads();
        for (int i = tid; i < KTS; i += 256) {
            int j = t0 + i;
            float cx = pb[j * 3 + 0], cy = pb[j * 3 + 1], cz = pb[j * 3 + 2];
            tile[i] = make_float4(cx, cy, cz, fmaf(cz, cz, fmaf(cy, cy, cx * cx)));
        }
        __syncthreads();
        for (int s = 0; s < KTS / 32; s++) {
            if (bc > 32) knn_flush(wd, wi, bc, theta, lane);
            float4 c = tile[s * 32 + lane];
            float dot = fmaf(qz, c.z, fmaf(qy, c.y, qx * c.x));
            float d2  = fmaf(-2.f, dot, qsq + c.w);
            bool acc = d2 < theta;
            unsigned m = __ballot_sync(0xffffffffu, acc);
            if (m) {
                int off = __popc(m & ((1u << lane) - 1u));
                if (acc) {
                    wd[16 + bc + off] = d2;
                    wi[16 + bc + off] = t0 + s * 32 + lane;
                }
                bc += __popc(m);
            }
        }
    }
    if (bc > 0) knn_flush(wd, wi, bc, theta, lane);
    if (lane < 16)
        g_idx[((size_t)b * NN + q) * KK + lane] = wi[lane];
}

// ---------------------------------------------------------------------------
// Kernel 3: fused posenc + attn MLPs + softmax + combine + out projection.
// 1 warp per query; lane l owns channels l and l+32; K packed as f32x2 pairs.
// Weights pre-paired in smem: w2[j*32+l] = (w[j][l], w[j][l+32]).
// ---------------------------------------------------------------------------
#define AQ 8
#define SQSTRIDE 576   // 64*9 ull per query

__device__ __forceinline__ void mv16x64(const ull* __restrict__ Sq,
                                        const ull* __restrict__ w2, int l,
                                        ull aL[8], ull aH[8]) {
#pragma unroll
    for (int kp = 0; kp < 8; kp++) { aL[kp] = 0ull; aH[kp] = 0ull; }
#pragma unroll 4
    for (int j = 0; j < 64; j++) {
        ull wp = w2[j * 32 + l];
        float wl, wh;
        upk(wp, wl, wh);
        ull wl2 = pk(wl, wl);
        ull wh2 = pk(wh, wh);
        const ull* s = Sq + j * 9;
#pragma unroll
        for (int kp = 0; kp < 8; kp++) {
            ull s2 = s[kp];
            aL[kp] = f2fma(s2, wl2, aL[kp]);
            aH[kp] = f2fma(s2, wh2, aH[kp]);
        }
    }
}

__global__ void __launch_bounds__(256) attn_kernel(
        const float* __restrict__ pos, const float* __restrict__ feat,
        const float* __restrict__ pe_w1, const float* __restrict__ pe_b1,
        const float* __restrict__ pe_w2, const float* __restrict__ pe_b2,
        const float* __restrict__ at_w1, const float* __restrict__ at_b1,
        const float* __restrict__ at_w2, const float* __restrict__ at_b2,
        const float* __restrict__ out_w, const float* __restrict__ out_b,
        float* __restrict__ out) {
    extern __shared__ ull smu[];
    ull* w2_pe2 = smu;                   // 2048
    ull* w2_at1 = smu + 2048;
    ull* w2_at2 = smu + 4096;
    ull* Sp2    = smu + 6144;            // AQ*576
    float* w_out = (float*)(Sp2 + AQ * SQSTRIDE);  // 4096
    float* s_pe1 = w_out + 4096;         // 192
    float* s_b   = s_pe1 + 192;          // 320
    float* relb  = s_b + 320;            // AQ*64
    float* resb  = relb + AQ * 64;       // AQ*64
    int*   idxb  = (int*)(resb + AQ * 64);  // AQ*16

    int tid = threadIdx.x;
    for (int e = tid; e < 2048; e += 256) {
        int j = e >> 5, l2 = e & 31;
        w2_pe2[e] = pk(pe_w2[j * 64 + l2], pe_w2[j * 64 + l2 + 32]);
        w2_at1[e] = pk(at_w1[j * 64 + l2], at_w1[j * 64 + l2 + 32]);
        w2_at2[e] = pk(at_w2[j * 64 + l2], at_w2[j * 64 + l2 + 32]);
    }
    for (int e = tid; e < 4096; e += 256) w_out[e] = out_w[e];
    if (tid < 192) s_pe1[tid] = pe_w1[tid];
    if (tid < 64) {
        s_b[tid]       = pe_b1[tid];
        s_b[64 + tid]  = pe_b2[tid];
        s_b[128 + tid] = at_b1[tid];
        s_b[192 + tid] = at_b2[tid];
        s_b[256 + tid] = out_b[tid];
    }

    int wid = tid >> 5;
    int l   = tid & 31;
    int g   = blockIdx.x * AQ + wid;
    int bbase = g & ~(NN - 1);

    float q_lo = g_q[(size_t)g * CC + l];
    float q_hi = g_q[(size_t)g * CC + l + 32];

    if (l < KK) {
        int k = l;
        int ii = g_idx[(size_t)g * KK + k];
        idxb[wid * KK + k] = ii;
        size_t np = (size_t)(bbase + ii) * 3;
        size_t qp = (size_t)g * 3;
        relb[(wid * KK + k) * 4 + 0] = pos[np + 0] - pos[qp + 0];
        relb[(wid * KK + k) * 4 + 1] = pos[np + 1] - pos[qp + 1];
        relb[(wid * KK + k) * 4 + 2] = pos[np + 2] - pos[qp + 2];
    }
    __syncthreads();

    ull* Sq = Sp2 + wid * SQSTRIDE;

    // Stage A: pe1 = relu(rel @ pe_w1 + pe_b1) -> Sq (packed k-pairs)
    {
        float w0l = s_pe1[l],      w1l = s_pe1[64 + l],  w2l = s_pe1[128 + l];
        float w0h = s_pe1[l + 32], w1h = s_pe1[96 + l],  w2h = s_pe1[160 + l];
        float b1l = s_b[l], b1h = s_b[l + 32];
#pragma unroll
        for (int kp = 0; kp < 8; kp++) {
            const float* ra = relb + (wid * KK + 2 * kp) * 4;
            const float* rb = ra + 4;
            float pa = fmaxf(fmaf(ra[2], w2l, fmaf(ra[1], w1l, fmaf(ra[0], w0l, b1l))), 0.f);
            float pb = fmaxf(fmaf(rb[2], w2l, fmaf(rb[1], w1l, fmaf(rb[0], w0l, b1l))), 0.f);
            Sq[l * 9 + kp] = pk(pa, pb);
            float qa = fmaxf(fmaf(ra[2], w2h, fmaf(ra[1], w1h, fmaf(ra[0], w0h, b1h))), 0.f);
            float qb = fmaxf(fmaf(rb[2], w2h, fmaf(rb[1], w1h, fmaf(rb[0], w0h, b1h))), 0.f);
            Sq[(l + 32) * 9 + kp] = pk(qa, qb);
        }
    }
    __syncwarp();

    // Stage B: posenc = pe1 @ pe_w2 + pe_b2
    ull penL[8], penH[8];
    mv16x64(Sq, w2_pe2, l, penL, penH);
    {
        ull b2l = pk(s_b[64 + l], s_b[64 + l]);
        ull b2h = pk(s_b[64 + l + 32], s_b[64 + l + 32]);
#pragma unroll
        for (int kp = 0; kp < 8; kp++) {
            penL[kp] = f2add(penL[kp], b2l);
            penH[kp] = f2add(penH[kp], b2h);
        }
    }
    __syncwarp();

    // Stage C: h = q - k_feat + posenc -> Sq
#pragma unroll
    for (int kp = 0; kp < 8; kp++) {
        int i0 = idxb[wid * KK + 2 * kp];
        int i1 = idxb[wid * KK + 2 * kp + 1];
        float k0l = g_k[(size_t)(bbase + i0) * CC + l];
        float k1l = g_k[(size_t)(bbase + i1) * CC + l];
        float k0h = g_k[(size_t)(bbase + i0) * CC + l + 32];
        float k1h = g_k[(size_t)(bbase + i1) * CC + l + 32];
        float p0, p1;
        upk(penL[kp], p0, p1);
        Sq[l * 9 + kp] = pk(q_lo - k0l + p0, q_lo - k1l + p1);
        upk(penH[kp], p0, p1);
        Sq[(l + 32) * 9 + kp] = pk(q_hi - k0h + p0, q_hi - k1h + p1);
    }
    __syncwarp();

    // Stage D: a1 = relu(h @ at_w1 + at_b1) -> Sq
    ull aL[8], aH[8];
    mv16x64(Sq, w2_at1, l, aL, aH);
    __syncwarp();
    {
        float bl = s_b[128 + l], bh = s_b[128 + l + 32];
#pragma unroll
        for (int kp = 0; kp < 8; kp++) {
            float x, y;
            upk(aL[kp], x, y);
            Sq[l * 9 + kp] = pk(fmaxf(x + bl, 0.f), fmaxf(y + bl, 0.f));
            upk(aH[kp], x, y);
            Sq[(l + 32) * 9 + kp] = pk(fmaxf(x + bh, 0.f), fmaxf(y + bh, 0.f));
        }
    }
    __syncwarp();

    // Stage E: logits = (a1 @ at_w2 + at_b2) / 8
    mv16x64(Sq, w2_at2, l, aL, aH);
    float el[KK], eh[KK];
    {
        float bl = s_b[192 + l], bh = s_b[192 + l + 32];
#pragma unroll
        for (int kp = 0; kp < 8; kp++) {
            float x, y;
            upk(aL[kp], x, y);
            el[2 * kp] = (x + bl) * 0.125f; el[2 * kp + 1] = (y + bl) * 0.125f;
            upk(aH[kp], x, y);
            eh[2 * kp] = (x + bh) * 0.125f; eh[2 * kp + 1] = (y + bh) * 0.125f;
        }
    }

    // softmax over K per channel + combine with (v + posenc)
    float ml = el[0], mh = eh[0];
#pragma unroll
    for (int k = 1; k < KK; k++) { ml = fmaxf(ml, el[k]); mh = fmaxf(mh, eh[k]); }
    float sl = 0.f, sh = 0.f;
#pragma unroll
    for (int k = 0; k < KK; k++) {
        el[k] = __expf(el[k] - ml); sl += el[k];
        eh[k] = __expf(eh[k] - mh); sh += eh[k];
    }
    float il = 1.f / sl, ih = 1.f / sh;
    float res_lo = 0.f, res_hi = 0.f;
#pragma unroll
    for (int kp = 0; kp < 8; kp++) {
        int i0 = idxb[wid * KK + 2 * kp];
        int i1 = idxb[wid * KK + 2 * kp + 1];
        float v0l = g_v[(size_t)(bbase + i0) * CC + l];
        float v1l = g_v[(size_t)(bbase + i1) * CC + l];
        float v0h = g_v[(size_t)(bbase + i0) * CC + l + 32];
        float v1h = g_v[(size_t)(bbase + i1) * CC + l + 32];
        float p0, p1;
        upk(penL[kp], p0, p1);
        res_lo = fmaf(el[2 * kp] * il,     v0l + p0, res_lo);
        res_lo = fmaf(el[2 * kp + 1] * il, v1l + p1, res_lo);
        upk(penH[kp], p0, p1);
        res_hi = fmaf(eh[2 * kp] * ih,     v0h + p0, res_hi);
        res_hi = fmaf(eh[2 * kp + 1] * ih, v1h + p1, res_hi);
    }
    resb[wid * CC + l] = res_lo;
    resb[wid * CC + l + 32] = res_hi;
    __syncwarp();

    // final: out = res @ out_w + out_b + features
    {
        float ol = s_b[256 + l], oh = s_b[256 + l + 32];
#pragma unroll 4
        for (int j = 0; j < 64; j++) {
            float rj = resb[wid * CC + j];
            ol = fmaf(rj, w_out[j * 64 + l], ol);
            oh = fmaf(rj, w_out[j * 64 + l + 32], oh);
        }
        out[(size_t)g * CC + l]      = ol + feat[(size_t)g * CC + l];
        out[(size_t)g * CC + l + 32] = oh + feat[(size_t)g * CC + l + 32];
    }
}

// ---------------------------------------------------------------------------
extern "C" void kernel_launch(void* const* d_in, const int* in_sizes, int n_in,
                              void* d_out, int out_size) {
    const float* pos   = (const float*)d_in[0];
    const float* feat  = (const float*)d_in[1];
    const float* emb_w = (const float*)d_in[2];
    const float* emb_b = (const float*)d_in[3];
    const float* wq    = (const float*)d_in[4];
    const float* wk    = (const float*)d_in[5];
    const float* wv    = (const float*)d_in[6];
    const float* pe_w1 = (const float*)d_in[7];
    const float* pe_b1 = (const float*)d_in[8];
    const float* pe_w2 = (const float*)d_in[9];
    const float* pe_b2 = (const float*)d_in[10];
    const float* at_w1 = (const float*)d_in[11];
    const float* at_b1 = (const float*)d_in[12];
    const float* at_w2 = (const float*)d_in[13];
    const float* at_b2 = (const float*)d_in[14];
    const float* out_w = (const float*)d_in[15];
    const float* out_b = (const float*)d_in[16];
    float* out = (float*)d_out;

    int proj_smem = 4 * 64 * PWPAD * 4;
    int attn_smem = (6144 + AQ * SQSTRIDE) * 8
                  + (4096 + 192 + 320 + AQ * 64 * 2) * 4 + AQ * KK * 4;
    cudaFuncSetAttribute(proj_kernel, cudaFuncAttributeMaxDynamicSharedMemorySize, proj_smem);
    cudaFuncSetAttribute(attn_kernel, cudaFuncAttributeMaxDynamicSharedMemorySize, attn_smem);

    proj_kernel<<<BN / 64, 256, proj_smem>>>(feat, emb_w, emb_b, wq, wk, wv);
    knn_kernel<<<dim3(NN / KWARPS, BB), 256>>>(pos);
    attn_kernel<<<BN / AQ, 256, attn_smem>>>(pos, feat, pe_w1, pe_b1, pe_w2, pe_b2,
                                             at_w1, at_b1, at_w2, at_b2, out_w, out_b, out);
}

// round 4
// speedup vs baseline: 2.2989x; 1.0906x over previous
#include <cuda_runtime.h>
#include <math.h>
#include <float.h>

#define BB 2
#define NN 8192
#define KK 16
#define CC 64
#define BN (BB*NN)

typedef unsigned long long ull;

__device__ __forceinline__ ull pk(float a, float b) {
    ull d; asm("mov.b64 %0,{%1,%2};" : "=l"(d) : "f"(a), "f"(b)); return d;
}
__device__ __forceinline__ void upk(ull s, float& a, float& b) {
    asm("mov.b64 {%0,%1},%2;" : "=f"(a), "=f"(b) : "l"(s));
}
__device__ __forceinline__ ull f2fma(ull a, ull b, ull c) {
    ull d; asm("fma.rn.f32x2 %0,%1,%2,%3;" : "=l"(d) : "l"(a), "l"(b), "l"(c)); return d;
}
__device__ __forceinline__ ull f2add(ull a, ull b) {
    ull d; asm("add.rn.f32x2 %0,%1,%2;" : "=l"(d) : "l"(a), "l"(b)); return d;
}

// scratch (device globals — no runtime allocation)
__device__ ull    g_q2[BN*32];     // (q[row][l], q[row][l+32])
__device__ ull    g_k2[BN*32];
__device__ ull    g_v2[BN*32];
__device__ int    g_idx[BN*KK];
__device__ float4 g_pos4[BN];      // (x, y, z, ||p||^2)

// ---------------------------------------------------------------------------
// Kernel 0: precompute pos4 with the exact fmaf chain used everywhere.
// ---------------------------------------------------------------------------
__global__ void prep_kernel(const float* __restrict__ pos) {
    int i = blockIdx.x * 256 + threadIdx.x;
    float x = pos[3 * i], y = pos[3 * i + 1], z = pos[3 * i + 2];
    g_pos4[i] = make_float4(x, y, z, fmaf(z, z, fmaf(y, y, x * x)));
}

// ---------------------------------------------------------------------------
// Kernel 1: x = feat@emb_w + emb_b ; q/k/v = x@wq/wk/wv.
// Warp owns 16 rows; lane l owns channels l, l+32. Rows packed as f32x2
// pairs (stride 9). q/k/v accumulated in one pass: per j, 3 weight LDS.64
// + 8 row LDS.64 feed 48 FFMA2.
// ---------------------------------------------------------------------------
#define PW 4
__global__ void __launch_bounds__(128) proj_kernel(
        const float* __restrict__ feat,
        const float* __restrict__ emb_w, const float* __restrict__ emb_b,
        const float* __restrict__ wq, const float* __restrict__ wk,
        const float* __restrict__ wv) {
    extern __shared__ ull pu[];
    ull* we2 = pu;              // 2048
    ull* wq2 = pu + 2048;
    ull* wk2 = pu + 4096;
    ull* wv2 = pu + 6144;
    ull* Sbase = pu + 8192;     // PW * 576
    ull* ebp = Sbase + PW * 576; // 32

    int tid = threadIdx.x, lane = tid & 31, w = tid >> 5;
    for (int e = tid; e < 2048; e += 128) {
        int j = e >> 5, l2 = e & 31;
        we2[e] = pk(emb_w[j * 64 + l2], emb_w[j * 64 + l2 + 32]);
        wq2[e] = pk(wq[j * 64 + l2],   wq[j * 64 + l2 + 32]);
        wk2[e] = pk(wk[j * 64 + l2],   wk[j * 64 + l2 + 32]);
        wv2[e] = pk(wv[j * 64 + l2],   wv[j * 64 + l2 + 32]);
    }
    if (tid < 32) ebp[tid] = pk(emb_b[tid], emb_b[tid + 32]);

    int rows = (blockIdx.x * PW + w) * 16;
    ull* S = Sbase + w * 576;

    // pack feat rows into S: S[j*9+rp] = (feat[2rp][j], feat[2rp+1][j])
#pragma unroll
    for (int rp = 0; rp < 8; rp++) {
        const float* f0 = feat + (size_t)(rows + 2 * rp) * 64;
        const float* f1 = f0 + 64;
        S[lane * 9 + rp]        = pk(f0[lane],      f1[lane]);
        S[(lane + 32) * 9 + rp] = pk(f0[lane + 32], f1[lane + 32]);
    }
    __syncthreads();

    // emb: x = feat @ emb_w + emb_b
    ull xL[8], xH[8];
    {
        float bl, bh;
        upk(ebp[lane], bl, bh);
        ull bl2 = pk(bl, bl), bh2 = pk(bh, bh);
#pragma unroll
        for (int rp = 0; rp < 8; rp++) { xL[rp] = bl2; xH[rp] = bh2; }
    }
#pragma unroll 4
    for (int j = 0; j < 64; j++) {
        ull wp = we2[j * 32 + lane];
        float wl, wh;
        upk(wp, wl, wh);
        ull wl2 = pk(wl, wl), wh2 = pk(wh, wh);
        const ull* s = S + j * 9;
#pragma unroll
        for (int rp = 0; rp < 8; rp++) {
            ull s2 = s[rp];
            xL[rp] = f2fma(s2, wl2, xL[rp]);
            xH[rp] = f2fma(s2, wh2, xH[rp]);
        }
    }
    __syncwarp();
#pragma unroll
    for (int rp = 0; rp < 8; rp++) {
        S[lane * 9 + rp]        = xL[rp];
        S[(lane + 32) * 9 + rp] = xH[rp];
    }
    __syncwarp();

    // q/k/v in one pass
    ull qL[8], qH[8], kL[8], kH[8], vL[8], vH[8];
#pragma unroll
    for (int rp = 0; rp < 8; rp++) {
        qL[rp] = qH[rp] = kL[rp] = kH[rp] = vL[rp] = vH[rp] = 0ull;
    }
#pragma unroll 2
    for (int j = 0; j < 64; j++) {
        float a, b;
        upk(wq2[j * 32 + lane], a, b);
        ull wql = pk(a, a), wqh = pk(b, b);
        upk(wk2[j * 32 + lane], a, b);
        ull wkl = pk(a, a), wkh = pk(b, b);
        upk(wv2[j * 32 + lane], a, b);
        ull wvl = pk(a, a), wvh = pk(b, b);
        const ull* s = S + j * 9;
#pragma unroll
        for (int rp = 0; rp < 8; rp++) {
            ull s2 = s[rp];
            qL[rp] = f2fma(s2, wql, qL[rp]);
            qH[rp] = f2fma(s2, wqh, qH[rp]);
            kL[rp] = f2fma(s2, wkl, kL[rp]);
            kH[rp] = f2fma(s2, wkh, kH[rp]);
            vL[rp] = f2fma(s2, wvl, vL[rp]);
            vH[rp] = f2fma(s2, wvh, vH[rp]);
        }
    }

    // store packed pairs: g_*2[row*32+l] = (val[row][l], val[row][l+32])
#pragma unroll
    for (int rp = 0; rp < 8; rp++) {
        size_t r0 = (size_t)(rows + 2 * rp) * 32 + lane;
        size_t r1 = r0 + 32;
        float a0, a1, b0, b1;
        upk(qL[rp], a0, a1); upk(qH[rp], b0, b1);
        g_q2[r0] = pk(a0, b0); g_q2[r1] = pk(a1, b1);
        upk(kL[rp], a0, a1); upk(kH[rp], b0, b1);
        g_k2[r0] = pk(a0, b0); g_k2[r1] = pk(a1, b1);
        upk(vL[rp], a0, a1); upk(vH[rp], b0, b1);
        g_v2[r0] = pk(a0, b0); g_v2[r1] = pk(a1, b1);
    }
}

// ---------------------------------------------------------------------------
// Kernel 2: KNN, warp-per-query, shared threshold, rank-select flush
// (flush machinery unchanged from the validated R3 version).
// Candidates streamed from g_pos4 with one coalesced LDG.128 per lane-step.
// ---------------------------------------------------------------------------
#define KWARPS 8
#define FSLOTS 80

__device__ __noinline__ void knn_flush(float* wd, int* wi, int& bc,
                                       float& theta, int lane) {
    int n = 16 + bc;
    int i0 = lane, i1 = lane + 32, i2 = lane + 64;
    bool v0 = i0 < n, v1 = i1 < n, v2 = i2 < n;
    float ed0 = v0 ? wd[i0] : 0.f;  int ei0 = v0 ? wi[i0] : 0;
    float ed1 = v1 ? wd[i1] : 0.f;  int ei1 = v1 ? wi[i1] : 0;
    float ed2 = v2 ? wd[i2] : 0.f;  int ei2 = v2 ? wi[i2] : 0;
    int r0 = 0, r1 = 0, r2 = 0;
    for (int j = 0; j < n; j++) {
        float dj = wd[j]; int ij = wi[j];
        r0 += (dj < ed0) || (dj == ed0 && ij < ei0);
        r1 += (dj < ed1) || (dj == ed1 && ij < ei1);
        r2 += (dj < ed2) || (dj == ed2 && ij < ei2);
    }
    __syncwarp();
    if (v0 && r0 < 16) { wd[r0] = ed0; wi[r0] = ei0; }
    if (v1 && r1 < 16) { wd[r1] = ed1; wi[r1] = ei1; }
    if (v2 && r2 < 16) { wd[r2] = ed2; wi[r2] = ei2; }
    __syncwarp();
    theta = wd[15];
    bc = 0;
}

__global__ void __launch_bounds__(256) knn_kernel() {
    __shared__ float fd[KWARPS][FSLOTS];
    __shared__ int   fi[KWARPS][FSLOTS];

    int tid = threadIdx.x, lane = tid & 31, w = tid >> 5;
    int b = blockIdx.y;
    int q = blockIdx.x * KWARPS + w;
    const float4* pb4 = g_pos4 + (size_t)b * NN;
    float4 qv = pb4[q];
    float qx = qv.x, qy = qv.y, qz = qv.z, qsq = qv.w;

    float* wd = fd[w];
    int*   wi = fi[w];
    if (lane < 16) { wd[lane] = FLT_MAX; wi[lane] = -1 - lane; }
    __syncwarp();

    float theta = FLT_MAX;
    int bc = 0;

    for (int s = 0; s < NN / 32; s++) {
        float4 c = pb4[s * 32 + lane];
        float dot = fmaf(qz, c.z, fmaf(qy, c.y, qx * c.x));
        float d2  = fmaf(-2.f, dot, qsq + c.w);
        bool acc = d2 < theta;
        unsigned m = __ballot_sync(0xffffffffu, acc);
        if (m) {
            if (bc > 32) knn_flush(wd, wi, bc, theta, lane);
            // re-test against possibly tightened theta (still correct:
            // theta only shrinks; survivors of old theta may now fail)
            acc = d2 < theta;
            m = __ballot_sync(0xffffffffu, acc);
            if (m) {
                int off = __popc(m & ((1u << lane) - 1u));
                if (acc) {
                    wd[16 + bc + off] = d2;
                    wi[16 + bc + off] = s * 32 + lane;
                }
                bc += __popc(m);
            }
        }
    }
    if (bc > 0) knn_flush(wd, wi, bc, theta, lane);
    if (lane < 16)
        g_idx[((size_t)b * NN + q) * KK + lane] = wi[lane];
}

// ---------------------------------------------------------------------------
// Kernel 3: fused posenc + attn MLPs + softmax + combine + out projection.
// 1 warp per query; lane l owns channels l and l+32; K packed as f32x2 pairs.
// q/k/v gathered as packed pairs (1 LDG.64 each); rel from g_pos4.
// ---------------------------------------------------------------------------
#define AQ 8
#define SQSTRIDE 576

__device__ __forceinline__ void mv16x64(const ull* __restrict__ Sq,
                                        const ull* __restrict__ w2, int l,
                                        ull aL[8], ull aH[8]) {
#pragma unroll
    for (int kp = 0; kp < 8; kp++) { aL[kp] = 0ull; aH[kp] = 0ull; }
#pragma unroll 4
    for (int j = 0; j < 64; j++) {
        ull wp = w2[j * 32 + l];
        float wl, wh;
        upk(wp, wl, wh);
        ull wl2 = pk(wl, wl);
        ull wh2 = pk(wh, wh);
        const ull* s = Sq + j * 9;
#pragma unroll
        for (int kp = 0; kp < 8; kp++) {
            ull s2 = s[kp];
            aL[kp] = f2fma(s2, wl2, aL[kp]);
            aH[kp] = f2fma(s2, wh2, aH[kp]);
        }
    }
}

__global__ void __launch_bounds__(256) attn_kernel(
        const float* __restrict__ feat,
        const float* __restrict__ pe_w1, const float* __restrict__ pe_b1,
        const float* __restrict__ pe_w2, const float* __restrict__ pe_b2,
        const float* __restrict__ at_w1, const float* __restrict__ at_b1,
        const float* __restrict__ at_w2, const float* __restrict__ at_b2,
        const float* __restrict__ out_w, const float* __restrict__ out_b,
        float* __restrict__ out) {
    extern __shared__ ull smu[];
    ull* w2_pe2 = smu;                   // 2048
    ull* w2_at1 = smu + 2048;
    ull* w2_at2 = smu + 4096;
    ull* Sp2    = smu + 6144;            // AQ*576
    float* w_out = (float*)(Sp2 + AQ * SQSTRIDE);  // 4096
    float* s_pe1 = w_out + 4096;         // 192
    float* s_b   = s_pe1 + 192;          // 320
    float* relb  = s_b + 320;            // AQ*64
    float* resb  = relb + AQ * 64;       // AQ*64
    int*   idxb  = (int*)(resb + AQ * 64);  // AQ*16

    int tid = threadIdx.x;
    for (int e = tid; e < 2048; e += 256) {
        int j = e >> 5, l2 = e & 31;
        w2_pe2[e] = pk(pe_w2[j * 64 + l2], pe_w2[j * 64 + l2 + 32]);
        w2_at1[e] = pk(at_w1[j * 64 + l2], at_w1[j * 64 + l2 + 32]);
        w2_at2[e] = pk(at_w2[j * 64 + l2], at_w2[j * 64 + l2 + 32]);
    }
    for (int e = tid; e < 4096; e += 256) w_out[e] = out_w[e];
    if (tid < 192) s_pe1[tid] = pe_w1[tid];
    if (tid < 64) {
        s_b[tid]       = pe_b1[tid];
        s_b[64 + tid]  = pe_b2[tid];
        s_b[128 + tid] = at_b1[tid];
        s_b[192 + tid] = at_b2[tid];
        s_b[256 + tid] = out_b[tid];
    }

    int wid = tid >> 5;
    int l   = tid & 31;
    int g   = blockIdx.x * AQ + wid;
    int bbase = g & ~(NN - 1);

    float q_lo, q_hi;
    upk(g_q2[(size_t)g * 32 + l], q_lo, q_hi);

    if (l < KK) {
        int ii = g_idx[(size_t)g * KK + l];
        idxb[wid * KK + l] = ii;
        float4 np = g_pos4[bbase + ii];
        float4 qp = g_pos4[g];
        relb[(wid * KK + l) * 4 + 0] = np.x - qp.x;
        relb[(wid * KK + l) * 4 + 1] = np.y - qp.y;
        relb[(wid * KK + l) * 4 + 2] = np.z - qp.z;
    }
    __syncthreads();

    ull* Sq = Sp2 + wid * SQSTRIDE;

    // Stage A: pe1 = relu(rel @ pe_w1 + pe_b1)
    {
        float w0l = s_pe1[l],      w1l = s_pe1[64 + l],  w2l = s_pe1[128 + l];
        float w0h = s_pe1[l + 32], w1h = s_pe1[96 + l],  w2h = s_pe1[160 + l];
        float b1l = s_b[l], b1h = s_b[l + 32];
#pragma unroll
        for (int kp = 0; kp < 8; kp++) {
            const float* ra = relb + (wid * KK + 2 * kp) * 4;
            const float* rb = ra + 4;
            float pa = fmaxf(fmaf(ra[2], w2l, fmaf(ra[1], w1l, fmaf(ra[0], w0l, b1l))), 0.f);
            float pb = fmaxf(fmaf(rb[2], w2l, fmaf(rb[1], w1l, fmaf(rb[0], w0l, b1l))), 0.f);
            Sq[l * 9 + kp] = pk(pa, pb);
            float qa = fmaxf(fmaf(ra[2], w2h, fmaf(ra[1], w1h, fmaf(ra[0], w0h, b1h))), 0.f);
            float qb = fmaxf(fmaf(rb[2], w2h, fmaf(rb[1], w1h, fmaf(rb[0], w0h, b1h))), 0.f);
            Sq[(l + 32) * 9 + kp] = pk(qa, qb);
        }
    }
    __syncwarp();

    // Stage B: posenc = pe1 @ pe_w2 + pe_b2
    ull penL[8], penH[8];
    mv16x64(Sq, w2_pe2, l, penL, penH);
    {
        ull b2l = pk(s_b[64 + l], s_b[64 + l]);
        ull b2h = pk(s_b[64 + l + 32], s_b[64 + l + 32]);
#pragma unroll
        for (int kp = 0; kp < 8; kp++) {
            penL[kp] = f2add(penL[kp], b2l);
            penH[kp] = f2add(penH[kp], b2h);
        }
    }
    __syncwarp();

    // Stage C: h = q - k_feat + posenc
#pragma unroll
    for (int kp = 0; kp < 8; kp++) {
        int i0 = idxb[wid * KK + 2 * kp];
        int i1 = idxb[wid * KK + 2 * kp + 1];
        float k0l, k0h, k1l, k1h;
        upk(g_k2[(size_t)(bbase + i0) * 32 + l], k0l, k0h);
        upk(g_k2[(size_t)(bbase + i1) * 32 + l], k1l, k1h);
        float p0, p1;
        upk(penL[kp], p0, p1);
        Sq[l * 9 + kp] = pk(q_lo - k0l + p0, q_lo - k1l + p1);
        upk(penH[kp], p0, p1);
        Sq[(l + 32) * 9 + kp] = pk(q_hi - k0h + p0, q_hi - k1h + p1);
    }
    __syncwarp();

    // Stage D: a1 = relu(h @ at_w1 + at_b1)
    ull aL[8], aH[8];
    mv16x64(Sq, w2_at1, l, aL, aH);
    __syncwarp();
    {
        float bl = s_b[128 + l], bh = s_b[128 + l + 32];
#pragma unroll
        for (int kp = 0; kp < 8; kp++) {
            float x, y;
            upk(aL[kp], x, y);
            Sq[l * 9 + kp] = pk(fmaxf(x + bl, 0.f), fmaxf(y + bl, 0.f));
            upk(aH[kp], x, y);
            Sq[(l + 32) * 9 + kp] = pk(fmaxf(x + bh, 0.f), fmaxf(y + bh, 0.f));
        }
    }
    __syncwarp();

    // Stage E: logits = (a1 @ at_w2 + at_b2) / 8
    mv16x64(Sq, w2_at2, l, aL, aH);
    float el[KK], eh[KK];
    {
        float bl = s_b[192 + l], bh = s_b[192 + l + 32];
#pragma unroll
        for (int kp = 0; kp < 8; kp++) {
            float x, y;
            upk(aL[kp], x, y);
            el[2 * kp] = (x + bl) * 0.125f; el[2 * kp + 1] = (y + bl) * 0.125f;
            upk(aH[kp], x, y);
            eh[2 * kp] = (x + bh) * 0.125f; eh[2 * kp + 1] = (y + bh) * 0.125f;
        }
    }

    // softmax over K per channel + combine with (v + posenc)
    float ml = el[0], mh = eh[0];
#pragma unroll
    for (int k = 1; k < KK; k++) { ml = fmaxf(ml, el[k]); mh = fmaxf(mh, eh[k]); }
    float sl = 0.f, sh = 0.f;
#pragma unroll
    for (int k = 0; k < KK; k++) {
        el[k] = __expf(el[k] - ml); sl += el[k];
        eh[k] = __expf(eh[k] - mh); sh += eh[k];
    }
    float il = 1.f / sl, ih = 1.f / sh;
    float res_lo = 0.f, res_hi = 0.f;
#pragma unroll
    for (int kp = 0; kp < 8; kp++) {
        int i0 = idxb[wid * KK + 2 * kp];
        int i1 = idxb[wid * KK + 2 * kp + 1];
        float v0l, v0h, v1l, v1h;
        upk(g_v2[(size_t)(bbase + i0) * 32 + l], v0l, v0h);
        upk(g_v2[(size_t)(bbase + i1) * 32 + l], v1l, v1h);
        float p0, p1;
        upk(penL[kp], p0, p1);
        res_lo = fmaf(el[2 * kp] * il,     v0l + p0, res_lo);
        res_lo = fmaf(el[2 * kp + 1] * il, v1l + p1, res_lo);
        upk(penH[kp], p0, p1);
        res_hi = fmaf(eh[2 * kp] * ih,     v0h + p0, res_hi);
        res_hi = fmaf(eh[2 * kp + 1] * ih, v1h + p1, res_hi);
    }
    resb[wid * CC + l] = res_lo;
    resb[wid * CC + l + 32] = res_hi;
    __syncwarp();

    // final: out = res @ out_w + out_b + features
    {
        float ol = s_b[256 + l], oh = s_b[256 + l + 32];
#pragma unroll 4
        for (int j = 0; j < 64; j++) {
            float rj = resb[wid * CC + j];
            ol = fmaf(rj, w_out[j * 64 + l], ol);
            oh = fmaf(rj, w_out[j * 64 + l + 32], oh);
        }
        out[(size_t)g * CC + l]      = ol + feat[(size_t)g * CC + l];
        out[(size_t)g * CC + l + 32] = oh + feat[(size_t)g * CC + l + 32];
    }
}

// ---------------------------------------------------------------------------
extern "C" void kernel_launch(void* const* d_in, const int* in_sizes, int n_in,
                              void* d_out, int out_size) {
    const float* pos   = (const float*)d_in[0];
    const float* feat  = (const float*)d_in[1];
    const float* emb_w = (const float*)d_in[2];
    const float* emb_b = (const float*)d_in[3];
    const float* wq    = (const float*)d_in[4];
    const float* wk    = (const float*)d_in[5];
    const float* wv    = (const float*)d_in[6];
    const float* pe_w1 = (const float*)d_in[7];
    const float* pe_b1 = (const float*)d_in[8];
    const float* pe_w2 = (const float*)d_in[9];
    const float* pe_b2 = (const float*)d_in[10];
    const float* at_w1 = (const float*)d_in[11];
    const float* at_b1 = (const float*)d_in[12];
    const float* at_w2 = (const float*)d_in[13];
    const float* at_b2 = (const float*)d_in[14];
    const float* out_w = (const float*)d_in[15];
    const float* out_b = (const float*)d_in[16];
    float* out = (float*)d_out;

    int proj_smem = (8192 + PW * 576 + 32) * 8;
    int attn_smem = (6144 + AQ * SQSTRIDE) * 8
                  + (4096 + 192 + 320 + AQ * 64 * 2) * 4 + AQ * KK * 4;
    cudaFuncSetAttribute(proj_kernel, cudaFuncAttributeMaxDynamicSharedMemorySize, proj_smem);
    cudaFuncSetAttribute(attn_kernel, cudaFuncAttributeMaxDynamicSharedMemorySize, attn_smem);

    prep_kernel<<<BN / 256, 256>>>(pos);
    proj_kernel<<<BN / (PW * 16), 128, proj_smem>>>(feat, emb_w, emb_b, wq, wk, wv);
    knn_kernel<<<dim3(NN / KWARPS, BB), 256>>>();
    attn_kernel<<<BN / AQ, 256, attn_smem>>>(feat, pe_w1, pe_b1, pe_w2, pe_b2,
                                             at_w1, at_b1, at_w2, at_b2, out_w, out_b, out);
}

// round 5
// speedup vs baseline: 2.3320x; 1.0144x over previous
#include <cuda_runtime.h>
#include <math.h>
#include <float.h>

#define BB 2
#define NN 8192
#define KK 16
#define CC 64
#define BN (BB*NN)

typedef unsigned long long ull;

__device__ __forceinline__ ull pk(float a, float b) {
    ull d; asm("mov.b64 %0,{%1,%2};" : "=l"(d) : "f"(a), "f"(b)); return d;
}
__device__ __forceinline__ void upk(ull s, float& a, float& b) {
    asm("mov.b64 {%0,%1},%2;" : "=f"(a), "=f"(b) : "l"(s));
}
__device__ __forceinline__ ull f2fma(ull a, ull b, ull c) {
    ull d; asm("fma.rn.f32x2 %0,%1,%2,%3;" : "=l"(d) : "l"(a), "l"(b), "l"(c)); return d;
}
__device__ __forceinline__ ull f2add(ull a, ull b) {
    ull d; asm("add.rn.f32x2 %0,%1,%2;" : "=l"(d) : "l"(a), "l"(b)); return d;
}

// scratch (device globals — no runtime allocation)
__device__ ull    g_q2[BN*32];     // (q[row][l], q[row][l+32])
__device__ ull    g_k2[BN*32];
__device__ ull    g_v2[BN*32];
__device__ int    g_idx[BN*KK];
__device__ float4 g_pos4[BN];      // (x, y, z, ||p||^2)

// ---------------------------------------------------------------------------
// Kernel 0: precompute pos4 with the exact fmaf chain used everywhere.
// ---------------------------------------------------------------------------
__global__ void prep_kernel(const float* __restrict__ pos) {
    int i = blockIdx.x * 256 + threadIdx.x;
    float x = pos[3 * i], y = pos[3 * i + 1], z = pos[3 * i + 2];
    g_pos4[i] = make_float4(x, y, z, fmaf(z, z, fmaf(y, y, x * x)));
}

// ---------------------------------------------------------------------------
// Kernel 1: x = feat@emb_w + emb_b ; q/k/v = x@wq/wk/wv.  (unchanged R4)
// ---------------------------------------------------------------------------
#define PW 4
__global__ void __launch_bounds__(128) proj_kernel(
        const float* __restrict__ feat,
        const float* __restrict__ emb_w, const float* __restrict__ emb_b,
        const float* __restrict__ wq, const float* __restrict__ wk,
        const float* __restrict__ wv) {
    extern __shared__ ull pu[];
    ull* we2 = pu;              // 2048
    ull* wq2 = pu + 2048;
    ull* wk2 = pu + 4096;
    ull* wv2 = pu + 6144;
    ull* Sbase = pu + 8192;     // PW * 576
    ull* ebp = Sbase + PW * 576; // 32

    int tid = threadIdx.x, lane = tid & 31, w = tid >> 5;
    for (int e = tid; e < 2048; e += 128) {
        int j = e >> 5, l2 = e & 31;
        we2[e] = pk(emb_w[j * 64 + l2], emb_w[j * 64 + l2 + 32]);
        wq2[e] = pk(wq[j * 64 + l2],   wq[j * 64 + l2 + 32]);
        wk2[e] = pk(wk[j * 64 + l2],   wk[j * 64 + l2 + 32]);
        wv2[e] = pk(wv[j * 64 + l2],   wv[j * 64 + l2 + 32]);
    }
    if (tid < 32) ebp[tid] = pk(emb_b[tid], emb_b[tid + 32]);

    int rows = (blockIdx.x * PW + w) * 16;
    ull* S = Sbase + w * 576;

#pragma unroll
    for (int rp = 0; rp < 8; rp++) {
        const float* f0 = feat + (size_t)(rows + 2 * rp) * 64;
        const float* f1 = f0 + 64;
        S[lane * 9 + rp]        = pk(f0[lane],      f1[lane]);
        S[(lane + 32) * 9 + rp] = pk(f0[lane + 32], f1[lane + 32]);
    }
    __syncthreads();

    ull xL[8], xH[8];
    {
        float bl, bh;
        upk(ebp[lane], bl, bh);
        ull bl2 = pk(bl, bl), bh2 = pk(bh, bh);
#pragma unroll
        for (int rp = 0; rp < 8; rp++) { xL[rp] = bl2; xH[rp] = bh2; }
    }
#pragma unroll 4
    for (int j = 0; j < 64; j++) {
        ull wp = we2[j * 32 + lane];
        float wl, wh;
        upk(wp, wl, wh);
        ull wl2 = pk(wl, wl), wh2 = pk(wh, wh);
        const ull* s = S + j * 9;
#pragma unroll
        for (int rp = 0; rp < 8; rp++) {
            ull s2 = s[rp];
            xL[rp] = f2fma(s2, wl2, xL[rp]);
            xH[rp] = f2fma(s2, wh2, xH[rp]);
        }
    }
    __syncwarp();
#pragma unroll
    for (int rp = 0; rp < 8; rp++) {
        S[lane * 9 + rp]        = xL[rp];
        S[(lane + 32) * 9 + rp] = xH[rp];
    }
    __syncwarp();

    ull qL[8], qH[8], kL[8], kH[8], vL[8], vH[8];
#pragma unroll
    for (int rp = 0; rp < 8; rp++) {
        qL[rp] = qH[rp] = kL[rp] = kH[rp] = vL[rp] = vH[rp] = 0ull;
    }
#pragma unroll 2
    for (int j = 0; j < 64; j++) {
        float a, b;
        upk(wq2[j * 32 + lane], a, b);
        ull wql = pk(a, a), wqh = pk(b, b);
        upk(wk2[j * 32 + lane], a, b);
        ull wkl = pk(a, a), wkh = pk(b, b);
        upk(wv2[j * 32 + lane], a, b);
        ull wvl = pk(a, a), wvh = pk(b, b);
        const ull* s = S + j * 9;
#pragma unroll
        for (int rp = 0; rp < 8; rp++) {
            ull s2 = s[rp];
            qL[rp] = f2fma(s2, wql, qL[rp]);
            qH[rp] = f2fma(s2, wqh, qH[rp]);
            kL[rp] = f2fma(s2, wkl, kL[rp]);
            kH[rp] = f2fma(s2, wkh, kH[rp]);
            vL[rp] = f2fma(s2, wvl, vL[rp]);
            vH[rp] = f2fma(s2, wvh, vH[rp]);
        }
    }

#pragma unroll
    for (int rp = 0; rp < 8; rp++) {
        size_t r0 = (size_t)(rows + 2 * rp) * 32 + lane;
        size_t r1 = r0 + 32;
        float a0, a1, b0, b1;
        upk(qL[rp], a0, a1); upk(qH[rp], b0, b1);
        g_q2[r0] = pk(a0, b0); g_q2[r1] = pk(a1, b1);
        upk(kL[rp], a0, a1); upk(kH[rp], b0, b1);
        g_k2[r0] = pk(a0, b0); g_k2[r1] = pk(a1, b1);
        upk(vL[rp], a0, a1); upk(vH[rp], b0, b1);
        g_v2[r0] = pk(a0, b0); g_v2[r1] = pk(a1, b1);
    }
}

// ---------------------------------------------------------------------------
// Kernel 2: KNN — smem-tiled candidates (8 warps share each tile load:
// L2 traffic /8 vs R4's private streams) + shared-threshold ballot buffer
// + rank-select flush (machinery unchanged, validated R3/R4).
// ---------------------------------------------------------------------------
#define KWARPS 8
#define FSLOTS 80
#define KTS 2048   // candidates per tile = 32KB

__device__ __noinline__ void knn_flush(float* wd, int* wi, int& bc,
                                       float& theta, int lane) {
    int n = 16 + bc;
    int i0 = lane, i1 = lane + 32, i2 = lane + 64;
    bool v0 = i0 < n, v1 = i1 < n, v2 = i2 < n;
    float ed0 = v0 ? wd[i0] : 0.f;  int ei0 = v0 ? wi[i0] : 0;
    float ed1 = v1 ? wd[i1] : 0.f;  int ei1 = v1 ? wi[i1] : 0;
    float ed2 = v2 ? wd[i2] : 0.f;  int ei2 = v2 ? wi[i2] : 0;
    int r0 = 0, r1 = 0, r2 = 0;
    for (int j = 0; j < n; j++) {
        float dj = wd[j]; int ij = wi[j];
        r0 += (dj < ed0) || (dj == ed0 && ij < ei0);
        r1 += (dj < ed1) || (dj == ed1 && ij < ei1);
        r2 += (dj < ed2) || (dj == ed2 && ij < ei2);
    }
    __syncwarp();
    if (v0 && r0 < 16) { wd[r0] = ed0; wi[r0] = ei0; }
    if (v1 && r1 < 16) { wd[r1] = ed1; wi[r1] = ei1; }
    if (v2 && r2 < 16) { wd[r2] = ed2; wi[r2] = ei2; }
    __syncwarp();
    theta = wd[15];
    bc = 0;
}

__global__ void __launch_bounds__(256) knn_kernel() {
    __shared__ float4 tile[KTS];
    __shared__ float fd[KWARPS][FSLOTS];
    __shared__ int   fi[KWARPS][FSLOTS];

    int tid = threadIdx.x, lane = tid & 31, w = tid >> 5;
    int b = blockIdx.y;
    int q = blockIdx.x * KWARPS + w;
    const float4* pb4 = g_pos4 + (size_t)b * NN;
    float4 qv = pb4[q];
    float qx = qv.x, qy = qv.y, qz = qv.z, qsq = qv.w;

    float* wd = fd[w];
    int*   wi = fi[w];
    if (lane < 16) { wd[lane] = FLT_MAX; wi[lane] = -1 - lane; }
    __syncwarp();

    float theta = FLT_MAX;
    int bc = 0;

    for (int t0 = 0; t0 < NN; t0 += KTS) {
        __syncthreads();
        for (int i = tid; i < KTS; i += 256)
            tile[i] = pb4[t0 + i];
        __syncthreads();
#pragma unroll 2
        for (int s = 0; s < KTS / 32; s++) {
            float4 c = tile[s * 32 + lane];
            float dot = fmaf(qz, c.z, fmaf(qy, c.y, qx * c.x));
            float d2  = fmaf(-2.f, dot, qsq + c.w);
            bool acc = d2 < theta;
            unsigned m = __ballot_sync(0xffffffffu, acc);
            if (m) {
                if (bc > 32) {
                    knn_flush(wd, wi, bc, theta, lane);
                    acc = d2 < theta;
                    m = __ballot_sync(0xffffffffu, acc);
                }
                if (m) {
                    int off = __popc(m & ((1u << lane) - 1u));
                    if (acc) {
                        wd[16 + bc + off] = d2;
                        wi[16 + bc + off] = t0 + s * 32 + lane;
                    }
                    bc += __popc(m);
                }
            }
        }
    }
    if (bc > 0) knn_flush(wd, wi, bc, theta, lane);
    if (lane < 16)
        g_idx[((size_t)b * NN + q) * KK + lane] = wi[lane];
}

// ---------------------------------------------------------------------------
// Kernel 3: fused posenc + attn MLPs + softmax + combine + out projection.
// Sq stride 10 (16B-aligned kp pairs) -> mv reads 4 broadcast LDS.128/j
// instead of 8 LDS.64. w_out read from gmem (L1-resident) to keep 2 blk/SM.
// ---------------------------------------------------------------------------
#define AQ 8
#define SQSTRIDE 640

__device__ __forceinline__ void mv16x64(const ull* __restrict__ Sq,
                                        const ull* __restrict__ w2, int l,
                                        ull aL[8], ull aH[8]) {
#pragma unroll
    for (int kp = 0; kp < 8; kp++) { aL[kp] = 0ull; aH[kp] = 0ull; }
#pragma unroll 4
    for (int j = 0; j < 64; j++) {
        ull wp = w2[j * 32 + l];
        float wl, wh;
        upk(wp, wl, wh);
        ull wl2 = pk(wl, wl);
        ull wh2 = pk(wh, wh);
        const ulonglong2* s = (const ulonglong2*)(Sq + j * 10);
#pragma unroll
        for (int kp2 = 0; kp2 < 4; kp2++) {
            ulonglong2 sv = s[kp2];
            aL[2 * kp2]     = f2fma(sv.x, wl2, aL[2 * kp2]);
            aH[2 * kp2]     = f2fma(sv.x, wh2, aH[2 * kp2]);
            aL[2 * kp2 + 1] = f2fma(sv.y, wl2, aL[2 * kp2 + 1]);
            aH[2 * kp2 + 1] = f2fma(sv.y, wh2, aH[2 * kp2 + 1]);
        }
    }
}

__global__ void __launch_bounds__(256) attn_kernel(
        const float* __restrict__ feat,
        const float* __restrict__ pe_w1, const float* __restrict__ pe_b1,
        const float* __restrict__ pe_w2, const float* __restrict__ pe_b2,
        const float* __restrict__ at_w1, const float* __restrict__ at_b1,
        const float* __restrict__ at_w2, const float* __restrict__ at_b2,
        const float* __restrict__ out_w, const float* __restrict__ out_b,
        float* __restrict__ out) {
    extern __shared__ ull smu[];
    ull* w2_pe2 = smu;                   // 2048
    ull* w2_at1 = smu + 2048;
    ull* w2_at2 = smu + 4096;
    ull* Sp2    = smu + 6144;            // AQ*640
    float* s_pe1 = (float*)(Sp2 + AQ * SQSTRIDE);  // 192
    float* s_b   = s_pe1 + 192;          // 320
    float* relb  = s_b + 320;            // AQ*64
    float* resb  = relb + AQ * 64;       // AQ*64
    int*   idxb  = (int*)(resb + AQ * 64);  // AQ*16

    int tid = threadIdx.x;
    for (int e = tid; e < 2048; e += 256) {
        int j = e >> 5, l2 = e & 31;
        w2_pe2[e] = pk(pe_w2[j * 64 + l2], pe_w2[j * 64 + l2 + 32]);
        w2_at1[e] = pk(at_w1[j * 64 + l2], at_w1[j * 64 + l2 + 32]);
        w2_at2[e] = pk(at_w2[j * 64 + l2], at_w2[j * 64 + l2 + 32]);
    }
    if (tid < 192) s_pe1[tid] = pe_w1[tid];
    if (tid < 64) {
        s_b[tid]       = pe_b1[tid];
        s_b[64 + tid]  = pe_b2[tid];
        s_b[128 + tid] = at_b1[tid];
        s_b[192 + tid] = at_b2[tid];
        s_b[256 + tid] = out_b[tid];
    }

    int wid = tid >> 5;
    int l   = tid & 31;
    int g   = blockIdx.x * AQ + wid;
    int bbase = g & ~(NN - 1);

    float q_lo, q_hi;
    upk(g_q2[(size_t)g * 32 + l], q_lo, q_hi);

    if (l < KK) {
        int ii = g_idx[(size_t)g * KK + l];
        idxb[wid * KK + l] = ii;
        float4 np = g_pos4[bbase + ii];
        float4 qp = g_pos4[g];
        relb[(wid * KK + l) * 4 + 0] = np.x - qp.x;
        relb[(wid * KK + l) * 4 + 1] = np.y - qp.y;
        relb[(wid * KK + l) * 4 + 2] = np.z - qp.z;
    }
    __syncthreads();

    ull* Sq = Sp2 + wid * SQSTRIDE;

    // Stage A: pe1 = relu(rel @ pe_w1 + pe_b1)
    {
        float w0l = s_pe1[l],      w1l = s_pe1[64 + l],  w2l = s_pe1[128 + l];
        float w0h = s_pe1[l + 32], w1h = s_pe1[96 + l],  w2h = s_pe1[160 + l];
        float b1l = s_b[l], b1h = s_b[l + 32];
#pragma unroll
        for (int kp = 0; kp < 8; kp++) {
            const float* ra = relb + (wid * KK + 2 * kp) * 4;
            const float* rb = ra + 4;
            float pa = fmaxf(fmaf(ra[2], w2l, fmaf(ra[1], w1l, fmaf(ra[0], w0l, b1l))), 0.f);
            float pb = fmaxf(fmaf(rb[2], w2l, fmaf(rb[1], w1l, fmaf(rb[0], w0l, b1l))), 0.f);
            Sq[l * 10 + kp] = pk(pa, pb);
            float qa = fmaxf(fmaf(ra[2], w2h, fmaf(ra[1], w1h, fmaf(ra[0], w0h, b1h))), 0.f);
            float qb = fmaxf(fmaf(rb[2], w2h, fmaf(rb[1], w1h, fmaf(rb[0], w0h, b1h))), 0.f);
            Sq[(l + 32) * 10 + kp] = pk(qa, qb);
        }
    }
    __syncwarp();

    // Stage B: posenc = pe1 @ pe_w2 + pe_b2
    ull penL[8], penH[8];
    mv16x64(Sq, w2_pe2, l, penL, penH);
    {
        ull b2l = pk(s_b[64 + l], s_b[64 + l]);
        ull b2h = pk(s_b[64 + l + 32], s_b[64 + l + 32]);
#pragma unroll
        for (int kp = 0; kp < 8; kp++) {
            penL[kp] = f2add(penL[kp], b2l);
            penH[kp] = f2add(penH[kp], b2h);
        }
    }
    __syncwarp();

    // Stage C: h = q - k_feat + posenc
#pragma unroll
    for (int kp = 0; kp < 8; kp++) {
        int i0 = idxb[wid * KK + 2 * kp];
        int i1 = idxb[wid * KK + 2 * kp + 1];
        float k0l, k0h, k1l, k1h;
        upk(g_k2[(size_t)(bbase + i0) * 32 + l], k0l, k0h);
        upk(g_k2[(size_t)(bbase + i1) * 32 + l], k1l, k1h);
        float p0, p1;
        upk(penL[kp], p0, p1);
        Sq[l * 10 + kp] = pk(q_lo - k0l + p0, q_lo - k1l + p1);
        upk(penH[kp], p0, p1);
        Sq[(l + 32) * 10 + kp] = pk(q_hi - k0h + p0, q_hi - k1h + p1);
    }
    __syncwarp();

    // Stage D: a1 = relu(h @ at_w1 + at_b1)
    ull aL[8], aH[8];
    mv16x64(Sq, w2_at1, l, aL, aH);
    __syncwarp();
    {
        float bl = s_b[128 + l], bh = s_b[128 + l + 32];
#pragma unroll
        for (int kp = 0; kp < 8; kp++) {
            float x, y;
            upk(aL[kp], x, y);
            Sq[l * 10 + kp] = pk(fmaxf(x + bl, 0.f), fmaxf(y + bl, 0.f));
            upk(aH[kp], x, y);
            Sq[(l + 32) * 10 + kp] = pk(fmaxf(x + bh, 0.f), fmaxf(y + bh, 0.f));
        }
    }
    __syncwarp();

    // Stage E: logits = (a1 @ at_w2 + at_b2) / 8
    mv16x64(Sq, w2_at2, l, aL, aH);
    float el[KK], eh[KK];
    {
        float bl = s_b[192 + l], bh = s_b[192 + l + 32];
#pragma unroll
        for (int kp = 0; kp < 8; kp++) {
            float x, y;
            upk(aL[kp], x, y);
            el[2 * kp] = (x + bl) * 0.125f; el[2 * kp + 1] = (y + bl) * 0.125f;
            upk(aH[kp], x, y);
            eh[2 * kp] = (x + bh) * 0.125f; eh[2 * kp + 1] = (y + bh) * 0.125f;
        }
    }

    // softmax over K per channel + combine with (v + posenc)
    float ml = el[0], mh = eh[0];
#pragma unroll
    for (int k = 1; k < KK; k++) { ml = fmaxf(ml, el[k]); mh = fmaxf(mh, eh[k]); }
    float sl = 0.f, sh = 0.f;
#pragma unroll
    for (int k = 0; k < KK; k++) {
        el[k] = __expf(el[k] - ml); sl += el[k];
        eh[k] = __expf(eh[k] - mh); sh += eh[k];
    }
    float il = 1.f / sl, ih = 1.f / sh;
    float res_lo = 0.f, res_hi = 0.f;
#pragma unroll
    for (int kp = 0; kp < 8; kp++) {
        int i0 = idxb[wid * KK + 2 * kp];
        int i1 = idxb[wid * KK + 2 * kp + 1];
        float v0l, v0h, v1l, v1h;
        upk(g_v2[(size_t)(bbase + i0) * 32 + l], v0l, v0h);
        upk(g_v2[(size_t)(bbase + i1) * 32 + l], v1l, v1h);
        float p0, p1;
        upk(penL[kp], p0, p1);
        res_lo = fmaf(el[2 * kp] * il,     v0l + p0, res_lo);
        res_lo = fmaf(el[2 * kp + 1] * il, v1l + p1, res_lo);
        upk(penH[kp], p0, p1);
        res_hi = fmaf(eh[2 * kp] * ih,     v0h + p0, res_hi);
        res_hi = fmaf(eh[2 * kp + 1] * ih, v1h + p1, res_hi);
    }
    resb[wid * CC + l] = res_lo;
    resb[wid * CC + l + 32] = res_hi;
    __syncwarp();

    // final: out = res @ out_w + out_b + features (out_w via L1)
    {
        float ol = s_b[256 + l], oh = s_b[256 + l + 32];
#pragma unroll 4
        for (int j = 0; j < 64; j++) {
            float rj = resb[wid * CC + j];
            ol = fmaf(rj, __ldg(&out_w[j * 64 + l]), ol);
            oh = fmaf(rj, __ldg(&out_w[j * 64 + l + 32]), oh);
        }
        out[(size_t)g * CC + l]      = ol + feat[(size_t)g * CC + l];
        out[(size_t)g * CC + l + 32] = oh + feat[(size_t)g * CC + l + 32];
    }
}

// ---------------------------------------------------------------------------
extern "C" void kernel_launch(void* const* d_in, const int* in_sizes, int n_in,
                              void* d_out, int out_size) {
    const float* pos   = (const float*)d_in[0];
    const float* feat  = (const float*)d_in[1];
    const float* emb_w = (const float*)d_in[2];
    const float* emb_b = (const float*)d_in[3];
    const float* wq    = (const float*)d_in[4];
    const float* wk    = (const float*)d_in[5];
    const float* wv    = (const float*)d_in[6];
    const float* pe_w1 = (const float*)d_in[7];
    const float* pe_b1 = (const float*)d_in[8];
    const float* pe_w2 = (const float*)d_in[9];
    const float* pe_b2 = (const float*)d_in[10];
    const float* at_w1 = (const float*)d_in[11];
    const float* at_b1 = (const float*)d_in[12];
    const float* at_w2 = (const float*)d_in[13];
    const float* at_b2 = (const float*)d_in[14];
    const float* out_w = (const float*)d_in[15];
    const float* out_b = (const float*)d_in[16];
    float* out = (float*)d_out;

    int proj_smem = (8192 + PW * 576 + 32) * 8;
    int attn_smem = (6144 + AQ * SQSTRIDE) * 8
                  + (192 + 320 + AQ * 64 * 2) * 4 + AQ * KK * 4;
    cudaFuncSetAttribute(proj_kernel, cudaFuncAttributeMaxDynamicSharedMemorySize, proj_smem);
    cudaFuncSetAttribute(attn_kernel, cudaFuncAttributeMaxDynamicSharedMemorySize, attn_smem);

    prep_kernel<<<BN / 256, 256>>>(pos);
    proj_kernel<<<BN / (PW * 16), 128, proj_smem>>>(feat, emb_w, emb_b, wq, wk, wv);
    knn_kernel<<<dim3(NN / KWARPS, BB), 256>>>();
    attn_kernel<<<BN / AQ, 256, attn_smem>>>(feat, pe_w1, pe_b1, pe_w2, pe_b2,
                                             at_w1, at_b1, at_w2, at_b2, out_w, out_b, out);
}